// round 3
// baseline (speedup 1.0000x reference)
#include <cuda_runtime.h>
#include <cstdint>

#define MTOK 8192
#define HID  2048
#define ITR  8192
#define NB   4
#define SEQ  2048
#define KSAVE 10

// ---------------- device scratch (no allocations allowed) ----------------
__device__ float g_y1[(size_t)MTOK * ITR];   // raw up-proj output (pre-relu), 256 MB
__device__ float g_pup[MTOK * 16];           // x1 @ w_up_lora_a
__device__ float g_pdn[MTOK * 16];           // relu(y1) @ w_down_lora_a
__device__ int   g_counts[NB * ITR];
__device__ int   g_topk[NB * KSAVE];

// ---------------- rank-16 projection: P[m][r] = sum_k act(A[m][k]) * Wl[k][r] ----
template<int RELU>
__global__ void lora_proj(const float* __restrict__ A, const float* __restrict__ Wl,
                          float* __restrict__ P, int K) {
    int row = blockIdx.x * 16 + (threadIdx.x >> 4);
    int r   = threadIdx.x & 15;
    const float* a = A + (size_t)row * K;
    float acc = 0.f;
    for (int k = 0; k < K; k += 4) {
        float4 av = *(const float4*)(a + k);
        if (RELU) {
            av.x = fmaxf(av.x, 0.f); av.y = fmaxf(av.y, 0.f);
            av.z = fmaxf(av.z, 0.f); av.w = fmaxf(av.w, 0.f);
        }
        acc += av.x * Wl[(k + 0) * 16 + r];
        acc += av.y * Wl[(k + 1) * 16 + r];
        acc += av.z * Wl[(k + 2) * 16 + r];
        acc += av.w * Wl[(k + 3) * 16 + r];
    }
    P[row * 16 + r] = acc;
}

// ---------------- 128x128x16 fp32 GEMM + rank-16 lora epilogue -----------------
// Y = act(A) @ W + L @ Bm     A:[M,K] row-major, W:[K,N], L:[M,16], Bm:[16,N]
template<int RELU_A, int SWAPXY>
__global__ __launch_bounds__(256, 2) void gemm128(
    const float* __restrict__ A, const float* __restrict__ W,
    const float* __restrict__ L, const float* __restrict__ Bm,
    float* __restrict__ Y, int M, int N, int K)
{
    __shared__ float As[16][136];   // 2176 floats; reused as sL[128][17] in epilogue
    __shared__ float Bs[16][128];

    int m0 = (SWAPXY ? blockIdx.x : blockIdx.y) * 128;
    int n0 = (SWAPXY ? blockIdx.y : blockIdx.x) * 128;
    int tid = threadIdx.x;
    int tx = tid & 15, ty = tid >> 4;

    float acc[8][8];
#pragma unroll
    for (int i = 0; i < 8; i++)
#pragma unroll
        for (int j = 0; j < 8; j++) acc[i][j] = 0.f;

    int am = tid >> 2;            // 0..63
    int ak = (tid & 3) << 2;      // 0,4,8,12
    int wk = tid >> 5;            // 0..7
    int wn = (tid & 31) << 2;     // 0..124

    const float* Aptr = A + (size_t)(m0 + am) * K + ak;
    const float* Wptr = W + (size_t)wk * N + n0 + wn;

    for (int k0 = 0; k0 < K; k0 += 16) {
        float4 a0 = *(const float4*)(Aptr);
        float4 a1 = *(const float4*)(Aptr + (size_t)64 * K);
        float4 w0 = *(const float4*)(Wptr);
        float4 w1 = *(const float4*)(Wptr + (size_t)8 * N);
        Aptr += 16;
        Wptr += (size_t)16 * N;
        if (RELU_A) {
            a0.x = fmaxf(a0.x, 0.f); a0.y = fmaxf(a0.y, 0.f);
            a0.z = fmaxf(a0.z, 0.f); a0.w = fmaxf(a0.w, 0.f);
            a1.x = fmaxf(a1.x, 0.f); a1.y = fmaxf(a1.y, 0.f);
            a1.z = fmaxf(a1.z, 0.f); a1.w = fmaxf(a1.w, 0.f);
        }
        __syncthreads();
        As[ak + 0][am] = a0.x; As[ak + 1][am] = a0.y;
        As[ak + 2][am] = a0.z; As[ak + 3][am] = a0.w;
        As[ak + 0][am + 64] = a1.x; As[ak + 1][am + 64] = a1.y;
        As[ak + 2][am + 64] = a1.z; As[ak + 3][am + 64] = a1.w;
        *(float4*)&Bs[wk][wn]     = w0;
        *(float4*)&Bs[wk + 8][wn] = w1;
        __syncthreads();

#pragma unroll
        for (int kk = 0; kk < 16; kk++) {
            float4 a0v = *(const float4*)&As[kk][ty * 4];
            float4 a1v = *(const float4*)&As[kk][64 + ty * 4];
            float4 b0v = *(const float4*)&Bs[kk][tx * 4];
            float4 b1v = *(const float4*)&Bs[kk][64 + tx * 4];
            float av[8] = {a0v.x, a0v.y, a0v.z, a0v.w, a1v.x, a1v.y, a1v.z, a1v.w};
            float bv[8] = {b0v.x, b0v.y, b0v.z, b0v.w, b1v.x, b1v.y, b1v.z, b1v.w};
#pragma unroll
            for (int i = 0; i < 8; i++)
#pragma unroll
                for (int j = 0; j < 8; j++) acc[i][j] += av[i] * bv[j];
        }
    }

    // ---------------- lora epilogue: acc += L[m,:] @ Bm[:,n] ----------------
    __syncthreads();
    {
        int r = tid >> 5;  // 0..7 : rows r and r+8
        *(float4*)&Bs[r][wn]     = *(const float4*)(Bm + (size_t)r * N + n0 + wn);
        *(float4*)&Bs[r + 8][wn] = *(const float4*)(Bm + (size_t)(r + 8) * N + n0 + wn);
    }
    float* sL = &As[0][0];  // 2176-float region -> [128][17]
    {
        const float* Lp = L + (size_t)m0 * 16;
        for (int i = tid; i < 2048; i += 256) {
            int row = i >> 4, rr = i & 15;
            sL[row * 17 + rr] = Lp[i];
        }
    }
    __syncthreads();
#pragma unroll
    for (int r = 0; r < 16; r++) {
        float4 b0v = *(const float4*)&Bs[r][tx * 4];
        float4 b1v = *(const float4*)&Bs[r][64 + tx * 4];
        float bv[8] = {b0v.x, b0v.y, b0v.z, b0v.w, b1v.x, b1v.y, b1v.z, b1v.w};
        float la[8];
#pragma unroll
        for (int i = 0; i < 4; i++) {
            la[i]     = sL[(ty * 4 + i) * 17 + r];
            la[4 + i] = sL[(64 + ty * 4 + i) * 17 + r];
        }
#pragma unroll
        for (int i = 0; i < 8; i++)
#pragma unroll
            for (int j = 0; j < 8; j++) acc[i][j] += la[i] * bv[j];
    }

    // ---------------- writeback ----------------
#pragma unroll
    for (int i = 0; i < 8; i++) {
        int row = (i < 4) ? (ty * 4 + i) : (64 + ty * 4 + (i - 4));
        float* yp = Y + (size_t)(m0 + row) * N + n0;
        *(float4*)(yp + tx * 4)      = make_float4(acc[i][0], acc[i][1], acc[i][2], acc[i][3]);
        *(float4*)(yp + 64 + tx * 4) = make_float4(acc[i][4], acc[i][5], acc[i][6], acc[i][7]);
    }
}

// ---------------- per-channel zero counts: x2==0 <=> y1<=0 ----------------
__global__ void count_zeros() {
    int c = blockIdx.x * 256 + threadIdx.x;
    int b = blockIdx.y;
    const float* p = g_y1 + (size_t)b * SEQ * ITR + c;
    int cnt = 0;
    for (int s = 0; s < SEQ; s++) cnt += (p[(size_t)s * ITR] <= 0.f) ? 1 : 0;
    g_counts[b * ITR + c] = cnt;
}

// ---------------- exact top-10 smallest (count, index), jax-stable tie-break ----
__global__ void topk_kernel() {
    __shared__ int red[256];
    int b = blockIdx.x, tid = threadIdx.x;
    int prev = -1;
    for (int r = 0; r < KSAVE; r++) {
        int best = 0x7fffffff;
        for (int c = tid; c < ITR; c += 256) {
            int key = (g_counts[b * ITR + c] << 13) | c;   // count<=2048 fits
            if (key > prev && key < best) best = key;
        }
        red[tid] = best;
        __syncthreads();
        for (int s = 128; s > 0; s >>= 1) {
            if (tid < s) red[tid] = min(red[tid], red[tid + s]);
            __syncthreads();
        }
        prev = red[0];
        if (tid == 0) g_topk[b * KSAVE + r] = prev & 8191;
        __syncthreads();
    }
}

// ---------------- gather x2_save[b][s][j] = relu(y1[b,s,topk[b][j]]) ----------
__global__ void gather_save(float* __restrict__ outp) {
    int i = blockIdx.x * 256 + threadIdx.x;
    if (i >= NB * SEQ * KSAVE) return;
    int j = i % KSAVE;
    int s = (i / KSAVE) % SEQ;
    int b = i / (KSAVE * SEQ);
    int c = g_topk[b * KSAVE + j];
    float v = g_y1[(size_t)(b * SEQ + s) * ITR + c];
    outp[i] = fmaxf(v, 0.f);
}

// ---------------- launch ----------------
extern "C" void kernel_launch(void* const* d_in, const int* in_sizes, int n_in,
                              void* d_out, int out_size) {
    const float* x1       = (const float*)d_in[0];
    const float* w_up     = (const float*)d_in[1];
    const float* w_up_la  = (const float*)d_in[2];
    const float* w_up_lb  = (const float*)d_in[3];
    const float* w_down   = (const float*)d_in[4];
    const float* w_dn_la  = (const float*)d_in[5];
    const float* w_dn_lb  = (const float*)d_in[6];
    float* out = (float*)d_out;

    float *y1, *pup, *pdn;
    cudaGetSymbolAddress((void**)&y1,  g_y1);
    cudaGetSymbolAddress((void**)&pup, g_pup);
    cudaGetSymbolAddress((void**)&pdn, g_pdn);

    // up projection (lora folded via epilogue); y1 kept raw (pre-relu)
    lora_proj<0><<<MTOK / 16, 256>>>(x1, w_up_la, pup, HID);
    gemm128<0, 1><<<dim3(MTOK / 128, ITR / 128), 256>>>(
        x1, w_up, pup, w_up_lb, y1, MTOK, ITR, HID);

    // channel selection path
    count_zeros<<<dim3(ITR / 256, NB), 256>>>();
    topk_kernel<<<NB, 256>>>();

    // down projection on relu(y1)
    lora_proj<1><<<MTOK / 16, 256>>>(y1, w_dn_la, pdn, ITR);
    gemm128<1, 0><<<dim3(HID / 128, MTOK / 128), 256>>>(
        y1, w_down, pdn, w_dn_lb, out, MTOK, HID, ITR);

    // sparse-save gather, appended after y2 in the output buffer
    int save_elems = NB * SEQ * KSAVE;
    gather_save<<<(save_elems + 255) / 256, 256>>>(out + (out_size - save_elems));
}

// round 4
// speedup vs baseline: 1.0543x; 1.0543x over previous
#include <cuda_runtime.h>
#include <cstdint>

#define MTOK 8192
#define HID  2048
#define ITR  8192
#define NB   4
#define SEQ  2048
#define KSAVE 10

// ---------------- device scratch (no allocations allowed) ----------------
__device__ float g_y1[(size_t)MTOK * ITR];   // raw up-proj output (pre-relu), 256 MB
__device__ float g_pup[MTOK * 16];           // x1 @ w_up_lora_a
__device__ float g_pdn[MTOK * 16];           // relu(y1) @ w_down_lora_a
__device__ int   g_counts[NB * ITR];
__device__ int   g_topk[NB * KSAVE];

// ---------------- rank-16 projection: P[m][r] = sum_k act(A[m][k]) * Wl[k][r] ----
template<int RELU>
__global__ void lora_proj(const float* __restrict__ A, const float* __restrict__ Wl,
                          float* __restrict__ P, int K) {
    int row = blockIdx.x * 16 + (threadIdx.x >> 4);
    int r   = threadIdx.x & 15;
    const float* a = A + (size_t)row * K;
    float acc = 0.f;
    for (int k = 0; k < K; k += 4) {
        float4 av = *(const float4*)(a + k);
        if (RELU) {
            av.x = fmaxf(av.x, 0.f); av.y = fmaxf(av.y, 0.f);
            av.z = fmaxf(av.z, 0.f); av.w = fmaxf(av.w, 0.f);
        }
        acc += av.x * Wl[(k + 0) * 16 + r];
        acc += av.y * Wl[(k + 1) * 16 + r];
        acc += av.z * Wl[(k + 2) * 16 + r];
        acc += av.w * Wl[(k + 3) * 16 + r];
    }
    P[row * 16 + r] = acc;
}

// ---------------- 128x128x16 fp32 GEMM + rank-16 lora epilogue -----------------
// Y = act(A) @ W + L @ Bm     A:[M,K] row-major, W:[K,N], L:[M,16], Bm:[16,N]
template<int RELU_A, int SWAPXY>
__global__ __launch_bounds__(256, 2) void gemm128(
    const float* __restrict__ A, const float* __restrict__ W,
    const float* __restrict__ L, const float* __restrict__ Bm,
    float* __restrict__ Y, int M, int N, int K)
{
    __shared__ float As[16][136];   // 2176 floats; reused as sL[128][17] in epilogue
    __shared__ float Bs[16][128];

    int m0 = (SWAPXY ? blockIdx.x : blockIdx.y) * 128;
    int n0 = (SWAPXY ? blockIdx.y : blockIdx.x) * 128;
    int tid = threadIdx.x;
    int tx = tid & 15, ty = tid >> 4;

    float acc[8][8];
#pragma unroll
    for (int i = 0; i < 8; i++)
#pragma unroll
        for (int j = 0; j < 8; j++) acc[i][j] = 0.f;

    int am = tid >> 2;            // 0..63
    int ak = (tid & 3) << 2;      // 0,4,8,12
    int wk = tid >> 5;            // 0..7
    int wn = (tid & 31) << 2;     // 0..124

    const float* Aptr = A + (size_t)(m0 + am) * K + ak;
    const float* Wptr = W + (size_t)wk * N + n0 + wn;

    for (int k0 = 0; k0 < K; k0 += 16) {
        float4 a0 = *(const float4*)(Aptr);
        float4 a1 = *(const float4*)(Aptr + (size_t)64 * K);
        float4 w0 = *(const float4*)(Wptr);
        float4 w1 = *(const float4*)(Wptr + (size_t)8 * N);
        Aptr += 16;
        Wptr += (size_t)16 * N;
        if (RELU_A) {
            a0.x = fmaxf(a0.x, 0.f); a0.y = fmaxf(a0.y, 0.f);
            a0.z = fmaxf(a0.z, 0.f); a0.w = fmaxf(a0.w, 0.f);
            a1.x = fmaxf(a1.x, 0.f); a1.y = fmaxf(a1.y, 0.f);
            a1.z = fmaxf(a1.z, 0.f); a1.w = fmaxf(a1.w, 0.f);
        }
        __syncthreads();
        As[ak + 0][am] = a0.x; As[ak + 1][am] = a0.y;
        As[ak + 2][am] = a0.z; As[ak + 3][am] = a0.w;
        As[ak + 0][am + 64] = a1.x; As[ak + 1][am + 64] = a1.y;
        As[ak + 2][am + 64] = a1.z; As[ak + 3][am + 64] = a1.w;
        *(float4*)&Bs[wk][wn]     = w0;
        *(float4*)&Bs[wk + 8][wn] = w1;
        __syncthreads();

#pragma unroll
        for (int kk = 0; kk < 16; kk++) {
            float4 a0v = *(const float4*)&As[kk][ty * 4];
            float4 a1v = *(const float4*)&As[kk][64 + ty * 4];
            float4 b0v = *(const float4*)&Bs[kk][tx * 4];
            float4 b1v = *(const float4*)&Bs[kk][64 + tx * 4];
            float av[8] = {a0v.x, a0v.y, a0v.z, a0v.w, a1v.x, a1v.y, a1v.z, a1v.w};
            float bv[8] = {b0v.x, b0v.y, b0v.z, b0v.w, b1v.x, b1v.y, b1v.z, b1v.w};
#pragma unroll
            for (int i = 0; i < 8; i++)
#pragma unroll
                for (int j = 0; j < 8; j++) acc[i][j] += av[i] * bv[j];
        }
    }

    // ---------------- lora epilogue: acc += L[m,:] @ Bm[:,n] ----------------
    __syncthreads();
    {
        int r = tid >> 5;  // 0..7 : rows r and r+8
        *(float4*)&Bs[r][wn]     = *(const float4*)(Bm + (size_t)r * N + n0 + wn);
        *(float4*)&Bs[r + 8][wn] = *(const float4*)(Bm + (size_t)(r + 8) * N + n0 + wn);
    }
    float* sL = &As[0][0];  // 2176-float region -> [128][17]
    {
        const float* Lp = L + (size_t)m0 * 16;
        for (int i = tid; i < 2048; i += 256) {
            int row = i >> 4, rr = i & 15;
            sL[row * 17 + rr] = Lp[i];
        }
    }
    __syncthreads();
#pragma unroll
    for (int r = 0; r < 16; r++) {
        float4 b0v = *(const float4*)&Bs[r][tx * 4];
        float4 b1v = *(const float4*)&Bs[r][64 + tx * 4];
        float bv[8] = {b0v.x, b0v.y, b0v.z, b0v.w, b1v.x, b1v.y, b1v.z, b1v.w};
        float la[8];
#pragma unroll
        for (int i = 0; i < 4; i++) {
            la[i]     = sL[(ty * 4 + i) * 17 + r];
            la[4 + i] = sL[(64 + ty * 4 + i) * 17 + r];
        }
#pragma unroll
        for (int i = 0; i < 8; i++)
#pragma unroll
            for (int j = 0; j < 8; j++) acc[i][j] += la[i] * bv[j];
    }

    // ---------------- writeback ----------------
#pragma unroll
    for (int i = 0; i < 8; i++) {
        int row = (i < 4) ? (ty * 4 + i) : (64 + ty * 4 + (i - 4));
        float* yp = Y + (size_t)(m0 + row) * N + n0;
        *(float4*)(yp + tx * 4)      = make_float4(acc[i][0], acc[i][1], acc[i][2], acc[i][3]);
        *(float4*)(yp + 64 + tx * 4) = make_float4(acc[i][4], acc[i][5], acc[i][6], acc[i][7]);
    }
}

// ---------------- per-channel zero counts: x2==0 <=> y1<=0 ----------------
__global__ void count_zeros() {
    int c = blockIdx.x * 256 + threadIdx.x;
    int b = blockIdx.y;
    const float* p = g_y1 + (size_t)b * SEQ * ITR + c;
    int cnt = 0;
    for (int s = 0; s < SEQ; s++) cnt += (p[(size_t)s * ITR] <= 0.f) ? 1 : 0;
    g_counts[b * ITR + c] = cnt;
}

// ---------------- exact top-10 smallest (count, index), jax-stable tie-break ----
__global__ void topk_kernel() {
    __shared__ int red[256];
    int b = blockIdx.x, tid = threadIdx.x;
    int prev = -1;
    for (int r = 0; r < KSAVE; r++) {
        int best = 0x7fffffff;
        for (int c = tid; c < ITR; c += 256) {
            int key = (g_counts[b * ITR + c] << 13) | c;   // count<=2048 fits
            if (key > prev && key < best) best = key;
        }
        red[tid] = best;
        __syncthreads();
        for (int s = 128; s > 0; s >>= 1) {
            if (tid < s) red[tid] = min(red[tid], red[tid + s]);
            __syncthreads();
        }
        prev = red[0];
        if (tid == 0) g_topk[b * KSAVE + r] = prev & 8191;
        __syncthreads();
    }
}

// ---------------- gather x2_save[b][s][j] = relu(y1[b,s,topk[b][j]]) ----------
__global__ void gather_save(float* __restrict__ outp) {
    int i = blockIdx.x * 256 + threadIdx.x;
    if (i >= NB * SEQ * KSAVE) return;
    int j = i % KSAVE;
    int s = (i / KSAVE) % SEQ;
    int b = i / (KSAVE * SEQ);
    int c = g_topk[b * KSAVE + j];
    float v = g_y1[(size_t)(b * SEQ + s) * ITR + c];
    outp[i] = fmaxf(v, 0.f);
}

// ---------------- launch ----------------
extern "C" void kernel_launch(void* const* d_in, const int* in_sizes, int n_in,
                              void* d_out, int out_size) {
    const float* x1       = (const float*)d_in[0];
    const float* w_up     = (const float*)d_in[1];
    const float* w_up_la  = (const float*)d_in[2];
    const float* w_up_lb  = (const float*)d_in[3];
    const float* w_down   = (const float*)d_in[4];
    const float* w_dn_la  = (const float*)d_in[5];
    const float* w_dn_lb  = (const float*)d_in[6];
    float* out = (float*)d_out;

    float *y1, *pup, *pdn;
    cudaGetSymbolAddress((void**)&y1,  g_y1);
    cudaGetSymbolAddress((void**)&pup, g_pup);
    cudaGetSymbolAddress((void**)&pdn, g_pdn);

    // up projection (lora folded via epilogue); y1 kept raw (pre-relu)
    lora_proj<0><<<MTOK / 16, 256>>>(x1, w_up_la, pup, HID);
    gemm128<0, 1><<<dim3(MTOK / 128, ITR / 128), 256>>>(
        x1, w_up, pup, w_up_lb, y1, MTOK, ITR, HID);

    // channel selection path
    count_zeros<<<dim3(ITR / 256, NB), 256>>>();
    topk_kernel<<<NB, 256>>>();

    // down projection on relu(y1)
    lora_proj<1><<<MTOK / 16, 256>>>(y1, w_dn_la, pdn, ITR);
    gemm128<1, 0><<<dim3(HID / 128, MTOK / 128), 256>>>(
        y1, w_down, pdn, w_dn_lb, out, MTOK, HID, ITR);

    // sparse-save gather, appended after y2 in the output buffer
    int save_elems = NB * SEQ * KSAVE;
    gather_save<<<(save_elems + 255) / 256, 256>>>(out + (out_size - save_elems));
}

// round 8
// speedup vs baseline: 2.0906x; 1.9829x over previous
#include <cuda_runtime.h>
#include <cuda_bf16.h>
#include <cstdint>

#define MTOK 8192
#define HID  2048
#define ITR  8192
#define NB   4
#define SEQ  2048
#define KSAVE 10
#define FLAG_CAP (1<<20)
#define FIX_TAU 1e-4f

// ---------------- device scratch ----------------
__device__ float g_y1[(size_t)MTOK * ITR];           // raw up-proj (pre-relu), fp32, patched by fixup
__device__ __nv_bfloat16 g_x1h[(size_t)MTOK * HID], g_x1l[(size_t)MTOK * HID];
__device__ __nv_bfloat16 g_wupTh[(size_t)ITR * HID], g_wupTl[(size_t)ITR * HID];   // [N][K]
__device__ __nv_bfloat16 g_x2h[(size_t)MTOK * ITR], g_x2l[(size_t)MTOK * ITR];
__device__ __nv_bfloat16 g_wdnTh[(size_t)HID * ITR], g_wdnTl[(size_t)HID * ITR];   // [N][K]
__device__ float g_pup[MTOK * 16];
__device__ float g_pdn[MTOK * 16];
__device__ int   g_counts[NB * ITR];
__device__ int   g_topk[NB * KSAVE];
__device__ int   g_nflag;
__device__ int   g_flagm[FLAG_CAP];
__device__ int   g_flagc[FLAG_CAP];

// ---------------- small helpers ----------------
__device__ __forceinline__ void ldsm4(uint32_t& r0, uint32_t& r1, uint32_t& r2, uint32_t& r3, uint32_t addr) {
    asm volatile("ldmatrix.sync.aligned.m8n8.x4.shared.b16 {%0,%1,%2,%3}, [%4];\n"
                 : "=r"(r0), "=r"(r1), "=r"(r2), "=r"(r3) : "r"(addr));
}
__device__ __forceinline__ void mma16816(float* d, const uint32_t* a, const uint32_t* b) {
    asm volatile("mma.sync.aligned.m16n8k16.row.col.f32.bf16.bf16.f32 "
                 "{%0,%1,%2,%3}, {%4,%5,%6,%7}, {%8,%9}, {%0,%1,%2,%3};\n"
                 : "+f"(d[0]), "+f"(d[1]), "+f"(d[2]), "+f"(d[3])
                 : "r"(a[0]), "r"(a[1]), "r"(a[2]), "r"(a[3]), "r"(b[0]), "r"(b[1]));
}

// ---------------- init ----------------
__global__ void init_flags() { g_nflag = 0; }

// ---------------- fp32 -> bf16 hi/lo split (optionally relu) ----------------
__global__ void split_rows(const float* __restrict__ src, __nv_bfloat16* __restrict__ dh,
                           __nv_bfloat16* __restrict__ dl, size_t n4, int relu) {
    size_t i = (size_t)blockIdx.x * 256 + threadIdx.x;
    if (i >= n4) return;
    float4 v = ((const float4*)src)[i];
    float vv[4] = {v.x, v.y, v.z, v.w};
    union { __nv_bfloat16 h[4]; uint2 u; } H, L;
#pragma unroll
    for (int j = 0; j < 4; j++) {
        float x = relu ? fmaxf(vv[j], 0.f) : vv[j];
        __nv_bfloat16 h = __float2bfloat16(x);
        H.h[j] = h;
        L.h[j] = __float2bfloat16(x - __bfloat162float(h));
    }
    ((uint2*)dh)[i] = H.u;
    ((uint2*)dl)[i] = L.u;
}

// ---------------- fp32 [K][N] -> bf16 hi/lo [N][K] transpose split ----------------
__global__ void split_T(const float* __restrict__ src, __nv_bfloat16* __restrict__ dh,
                        __nv_bfloat16* __restrict__ dl, int K, int N) {
    __shared__ float t[32][33];
    int bx = blockIdx.x, by = blockIdx.y;        // n block, k block
    int x = threadIdx.x, y = threadIdx.y;        // 32 x 8
#pragma unroll
    for (int i = 0; i < 32; i += 8)
        t[y + i][x] = src[(size_t)(by * 32 + y + i) * N + bx * 32 + x];
    __syncthreads();
#pragma unroll
    for (int i = 0; i < 32; i += 8) {
        int nrow = bx * 32 + y + i;
        int kcol = by * 32 + x;
        float v = t[x][y + i];
        __nv_bfloat16 h = __float2bfloat16(v);
        dh[(size_t)nrow * K + kcol] = h;
        dl[(size_t)nrow * K + kcol] = __float2bfloat16(v - __bfloat162float(h));
    }
}

// ---------------- rank-16 projection (exact fp32) ----------------
template<int RELU>
__global__ void lora_proj(const float* __restrict__ A, const float* __restrict__ Wl,
                          float* __restrict__ P, int K) {
    int row = blockIdx.x * 16 + (threadIdx.x >> 4);
    int r   = threadIdx.x & 15;
    const float* a = A + (size_t)row * K;
    float acc = 0.f;
    for (int k = 0; k < K; k += 4) {
        float4 av = *(const float4*)(a + k);
        if (RELU) {
            av.x = fmaxf(av.x, 0.f); av.y = fmaxf(av.y, 0.f);
            av.z = fmaxf(av.z, 0.f); av.w = fmaxf(av.w, 0.f);
        }
        acc += av.x * Wl[(k + 0) * 16 + r];
        acc += av.y * Wl[(k + 1) * 16 + r];
        acc += av.z * Wl[(k + 2) * 16 + r];
        acc += av.w * Wl[(k + 3) * 16 + r];
    }
    P[row * 16 + r] = acc;
}

// ---------------- bf16x3 tensor-core GEMM: Y = A@B^T + L@Bm ----------------
// A (hi/lo): [M][K] bf16 row-major; B (hi/lo): [N][K] bf16 row-major (K-major)
// L: [M][16] fp32; Bm: [16][N] fp32
__device__ __forceinline__ void frag_loadA(uint32_t a[2][4], uint32_t base, int warpM, int s, int lane) {
    int rlo = lane & 15;
    int c4  = s * 2 + (lane >> 4);
#pragma unroll
    for (int mi = 0; mi < 2; mi++) {
        int row = warpM + mi * 16 + rlo;
        uint32_t ad = base + row * 64 + ((c4 ^ ((row >> 1) & 3)) << 4);
        ldsm4(a[mi][0], a[mi][1], a[mi][2], a[mi][3], ad);
    }
}
__device__ __forceinline__ void frag_loadB(uint32_t b[8][2], uint32_t base, int warpN, int s, int lane) {
    int rlo = lane & 15;
    int c4  = s * 2 + (lane >> 4);
#pragma unroll
    for (int nj = 0; nj < 4; nj++) {
        int row = warpN + nj * 16 + rlo;
        uint32_t ad = base + row * 64 + ((c4 ^ ((row >> 1) & 3)) << 4);
        uint32_t r0, r1, r2, r3;
        ldsm4(r0, r1, r2, r3, ad);
        b[2 * nj][0] = r0; b[2 * nj][1] = r2;
        b[2 * nj + 1][0] = r1; b[2 * nj + 1][1] = r3;
    }
}
__device__ __forceinline__ void mma_all(float acc[2][8][4], uint32_t a[2][4], uint32_t b[8][2]) {
#pragma unroll
    for (int mi = 0; mi < 2; mi++)
#pragma unroll
        for (int ni = 0; ni < 8; ni++) mma16816(acc[mi][ni], a[mi], b[ni]);
}

template<int SWAP>
__global__ void __launch_bounds__(256) gemm_bf16x3(
    const __nv_bfloat16* __restrict__ gAh, const __nv_bfloat16* __restrict__ gAl,
    const __nv_bfloat16* __restrict__ gBh, const __nv_bfloat16* __restrict__ gBl,
    const float* __restrict__ gL, const float* __restrict__ gBm,
    float* __restrict__ Y, int M, int N, int K)
{
    extern __shared__ char smem[];
    const int tid = threadIdx.x, lane = tid & 31, wid = tid >> 5;
    const int m0 = (SWAP ? blockIdx.y : blockIdx.x) * 128;
    const int n0 = (SWAP ? blockIdx.x : blockIdx.y) * 128;
    const int warpM = (wid >> 1) * 32, warpN = (wid & 1) * 64;

    float acc[2][8][4];
#pragma unroll
    for (int mi = 0; mi < 2; mi++)
#pragma unroll
        for (int ni = 0; ni < 8; ni++)
#pragma unroll
            for (int q = 0; q < 4; q++) acc[mi][ni][q] = 0.f;

    const __nv_bfloat16* srcs[4] = {gAh, gAl, gBh, gBl};

    // stage layout: stage s at smem + s*32768; arrays Ah/Al/Bh/Bl each 8KB (128 rows x 64B, swizzled)
    auto stage_load = [&](int st, int k0) {
        char* base = smem + st * 32768;
#pragma unroll
        for (int arr = 0; arr < 4; arr++) {
            int row0 = (arr < 2) ? m0 : n0;
            char* dst = base + arr * 8192;
#pragma unroll
            for (int i = 0; i < 2; i++) {
                int c = tid + i * 256;
                int row = c >> 2, c4 = c & 3;
                const __nv_bfloat16* g = srcs[arr] + (size_t)(row0 + row) * K + k0 + c4 * 8;
                uint32_t d = (uint32_t)__cvta_generic_to_shared(
                    dst + row * 64 + ((c4 ^ ((row >> 1) & 3)) << 4));
                asm volatile("cp.async.cg.shared.global [%0], [%1], 16;\n" :: "r"(d), "l"(g));
            }
        }
        asm volatile("cp.async.commit_group;\n");
    };

    stage_load(0, 0);
    for (int k0 = 0; k0 < K; k0 += 32) {
        int cur = (k0 >> 5) & 1;
        if (k0 + 32 < K) {
            stage_load(cur ^ 1, k0 + 32);
            asm volatile("cp.async.wait_group 1;\n");
        } else {
            asm volatile("cp.async.wait_group 0;\n");
        }
        __syncthreads();
        uint32_t bA = (uint32_t)__cvta_generic_to_shared(smem + cur * 32768);
        uint32_t bAh = bA, bAl = bA + 8192, bBh = bA + 16384, bBl = bA + 24576;
#pragma unroll
        for (int s = 0; s < 2; s++) {
            uint32_t a[2][4], b[8][2];
            frag_loadA(a, bAh, warpM, s, lane);
            frag_loadB(b, bBh, warpN, s, lane);
            mma_all(acc, a, b);                       // Ah * Bh
            frag_loadA(a, bAl, warpM, s, lane);
            mma_all(acc, a, b);                       // Al * Bh
            frag_loadB(b, bBl, warpN, s, lane);
            frag_loadA(a, bAh, warpM, s, lane);
            mma_all(acc, a, b);                       // Ah * Bl
        }
        __syncthreads();
    }

    // ---------------- fp32 lora epilogue ----------------
    float* sL = (float*)smem;                 // [128][17]
    float* sB = (float*)(smem + 128 * 17 * 4); // [16][132]
    for (int i = tid; i < 128 * 16; i += 256) {
        int rw = i >> 4, rr = i & 15;
        sL[rw * 17 + rr] = gL[(size_t)(m0 + rw) * 16 + rr];
    }
    for (int i = tid; i < 16 * 128; i += 256) {
        int rr = i >> 7, cc = i & 127;
        sB[rr * 132 + cc] = gBm[(size_t)rr * N + n0 + cc];
    }
    __syncthreads();
    int r = lane >> 2, cb = (lane & 3) * 2;
#pragma unroll
    for (int rr = 0; rr < 16; rr++) {
        float L0 = sL[(warpM + r) * 17 + rr];
        float L1 = sL[(warpM + r + 8) * 17 + rr];
        float L2 = sL[(warpM + 16 + r) * 17 + rr];
        float L3 = sL[(warpM + 16 + r + 8) * 17 + rr];
#pragma unroll
        for (int ni = 0; ni < 8; ni++) {
            float b0v = sB[rr * 132 + warpN + ni * 8 + cb];
            float b1v = sB[rr * 132 + warpN + ni * 8 + cb + 1];
            acc[0][ni][0] += L0 * b0v; acc[0][ni][1] += L0 * b1v;
            acc[0][ni][2] += L1 * b0v; acc[0][ni][3] += L1 * b1v;
            acc[1][ni][0] += L2 * b0v; acc[1][ni][1] += L2 * b1v;
            acc[1][ni][2] += L3 * b0v; acc[1][ni][3] += L3 * b1v;
        }
    }
    // ---------------- writeback ----------------
#pragma unroll
    for (int mi = 0; mi < 2; mi++) {
        int row0 = m0 + warpM + mi * 16 + r;
#pragma unroll
        for (int ni = 0; ni < 8; ni++) {
            int col = n0 + warpN + ni * 8 + cb;
            *(float2*)&Y[(size_t)row0 * N + col]       = make_float2(acc[mi][ni][0], acc[mi][ni][1]);
            *(float2*)&Y[(size_t)(row0 + 8) * N + col] = make_float2(acc[mi][ni][2], acc[mi][ni][3]);
        }
    }
}

// ---------------- counts + near-zero flagging ----------------
__global__ void count_flag() {
    int c = blockIdx.x * 256 + threadIdx.x;
    int b = blockIdx.y;
    const float* p = g_y1 + (size_t)b * SEQ * ITR + c;
    int cnt = 0;
    for (int s = 0; s < SEQ; s++) {
        float v = p[(size_t)s * ITR];
        cnt += (v <= 0.f) ? 1 : 0;
        if (fabsf(v) < FIX_TAU) {
            int slot = atomicAdd(&g_nflag, 1);
            if (slot < FLAG_CAP) { g_flagm[slot] = b * SEQ + s; g_flagc[slot] = c; }
        }
    }
    g_counts[b * ITR + c] = cnt;
}

// ---------------- exact fp32 recompute of flagged elements ----------------
__global__ void fixup(const float* __restrict__ x1, const float* __restrict__ w_up,
                      const float* __restrict__ w_up_lb) {
    int warpId = (blockIdx.x * blockDim.x + threadIdx.x) >> 5;
    int lane = threadIdx.x & 31;
    int totalWarps = (gridDim.x * blockDim.x) >> 5;
    int n = min(g_nflag, FLAG_CAP);
    for (int i = warpId; i < n; i += totalWarps) {
        int m = g_flagm[i], c = g_flagc[i];
        const float* xr = x1 + (size_t)m * HID;
        float s = 0.f;
        for (int k = lane; k < HID; k += 32) s += xr[k] * w_up[(size_t)k * ITR + c];
#pragma unroll
        for (int o = 16; o > 0; o >>= 1) s += __shfl_xor_sync(0xffffffffu, s, o);
        if (lane == 0) {
#pragma unroll
            for (int rr = 0; rr < 16; rr++) s += g_pup[m * 16 + rr] * w_up_lb[rr * ITR + c];
            float old = g_y1[(size_t)m * ITR + c];
            bool zo = (old <= 0.f), zn = (s <= 0.f);
            if (zo != zn) atomicAdd(&g_counts[(m >> 11) * ITR + c], zn ? 1 : -1);
            g_y1[(size_t)m * ITR + c] = s;
        }
    }
}

// ---------------- exact top-10 smallest (count, index) ----------------
__global__ void topk_kernel() {
    __shared__ int red[256];
    int b = blockIdx.x, tid = threadIdx.x;
    int prev = -1;
    for (int r = 0; r < KSAVE; r++) {
        int best = 0x7fffffff;
        for (int c = tid; c < ITR; c += 256) {
            int key = (g_counts[b * ITR + c] << 13) | c;
            if (key > prev && key < best) best = key;
        }
        red[tid] = best;
        __syncthreads();
        for (int s = 128; s > 0; s >>= 1) {
            if (tid < s) red[tid] = min(red[tid], red[tid + s]);
            __syncthreads();
        }
        prev = red[0];
        if (tid == 0) g_topk[b * KSAVE + r] = prev & 8191;
        __syncthreads();
    }
}

// ---------------- gather ----------------
__global__ void gather_save(float* __restrict__ outp) {
    int i = blockIdx.x * 256 + threadIdx.x;
    if (i >= NB * SEQ * KSAVE) return;
    int j = i % KSAVE;
    int s = (i / KSAVE) % SEQ;
    int b = i / (KSAVE * SEQ);
    int c = g_topk[b * KSAVE + j];
    float v = g_y1[(size_t)(b * SEQ + s) * ITR + c];
    outp[i] = fmaxf(v, 0.f);
}

// ---------------- launch ----------------
extern "C" void kernel_launch(void* const* d_in, const int* in_sizes, int n_in,
                              void* d_out, int out_size) {
    const float* x1      = (const float*)d_in[0];
    const float* w_up    = (const float*)d_in[1];
    const float* w_up_la = (const float*)d_in[2];
    const float* w_up_lb = (const float*)d_in[3];
    const float* w_down  = (const float*)d_in[4];
    const float* w_dn_la = (const float*)d_in[5];
    const float* w_dn_lb = (const float*)d_in[6];
    float* out = (float*)d_out;

    float *y1, *pup, *pdn;
    __nv_bfloat16 *x1h, *x1l, *wupTh, *wupTl, *x2h, *x2l, *wdnTh, *wdnTl;
    cudaGetSymbolAddress((void**)&y1, g_y1);
    cudaGetSymbolAddress((void**)&pup, g_pup);
    cudaGetSymbolAddress((void**)&pdn, g_pdn);
    cudaGetSymbolAddress((void**)&x1h, g_x1h);
    cudaGetSymbolAddress((void**)&x1l, g_x1l);
    cudaGetSymbolAddress((void**)&wupTh, g_wupTh);
    cudaGetSymbolAddress((void**)&wupTl, g_wupTl);
    cudaGetSymbolAddress((void**)&x2h, g_x2h);
    cudaGetSymbolAddress((void**)&x2l, g_x2l);
    cudaGetSymbolAddress((void**)&wdnTh, g_wdnTh);
    cudaGetSymbolAddress((void**)&wdnTl, g_wdnTl);

    cudaFuncSetAttribute(gemm_bf16x3<0>, cudaFuncAttributeMaxDynamicSharedMemorySize, 65536);
    cudaFuncSetAttribute(gemm_bf16x3<1>, cudaFuncAttributeMaxDynamicSharedMemorySize, 65536);

    init_flags<<<1, 1>>>();

    // ---- up projection ----
    lora_proj<0><<<MTOK / 16, 256>>>(x1, w_up_la, pup, HID);
    {
        size_t n4 = (size_t)MTOK * HID / 4;
        split_rows<<<(unsigned)((n4 + 255) / 256), 256>>>(x1, x1h, x1l, n4, 0);
    }
    split_T<<<dim3(ITR / 32, HID / 32), dim3(32, 8)>>>(w_up, wupTh, wupTl, HID, ITR);
    gemm_bf16x3<0><<<dim3(MTOK / 128, ITR / 128), 256, 65536>>>(
        x1h, x1l, wupTh, wupTl, pup, w_up_lb, y1, MTOK, ITR, HID);

    // ---- selection path (exact) ----
    count_flag<<<dim3(ITR / 256, NB), 256>>>();
    fixup<<<256, 256>>>(x1, w_up, w_up_lb);
    topk_kernel<<<NB, 256>>>();

    // ---- down projection ----
    lora_proj<1><<<MTOK / 16, 256>>>(y1, w_dn_la, pdn, ITR);
    {
        size_t n4 = (size_t)MTOK * ITR / 4;
        split_rows<<<(unsigned)((n4 + 255) / 256), 256>>>(y1, x2h, x2l, n4, 1);
    }
    split_T<<<dim3(HID / 32, ITR / 32), dim3(32, 8)>>>(w_down, wdnTh, wdnTl, ITR, HID);
    gemm_bf16x3<1><<<dim3(HID / 128, MTOK / 128), 256, 65536>>>(
        x2h, x2l, wdnTh, wdnTl, pdn, w_dn_lb, out, MTOK, HID, ITR);

    // ---- sparse save ----
    int save_elems = NB * SEQ * KSAVE;
    gather_save<<<(save_elems + 255) / 256, 256>>>(out + (out_size - save_elems));
}

// round 10
// speedup vs baseline: 2.5824x; 1.2352x over previous
#include <cuda_runtime.h>
#include <cuda_fp16.h>
#include <cstdint>

#define MTOK 8192
#define HID  2048
#define ITR  8192
#define NB   4
#define SEQ  2048
#define KSAVE 10
#define FLAG_CAP (1<<20)
#define FIX_TAU 2e-3f

// ---------------- device scratch ----------------
__device__ float g_y1[(size_t)MTOK * ITR];                 // raw up-proj (pre-relu), fixed up
__device__ __half g_x1h[(size_t)MTOK * HID], g_x1l[(size_t)MTOK * HID];
__device__ __half g_wupT[(size_t)ITR * HID];               // fp16 [N][K]
__device__ float  g_wupT32[(size_t)ITR * HID];             // fp32 [N][K] for exact fixup
__device__ __half g_x2h[(size_t)MTOK * ITR], g_x2l[(size_t)MTOK * ITR];
__device__ __half g_wdnT[(size_t)HID * ITR];               // fp16 [N][K]
__device__ float g_pup[MTOK * 16];
__device__ float g_pdn[MTOK * 16];
__device__ int   g_counts[NB * ITR];
__device__ int   g_topk[NB * KSAVE];
__device__ int   g_nflag;
__device__ int   g_flagm[FLAG_CAP];
__device__ int   g_flagc[FLAG_CAP];

// ---------------- helpers ----------------
__device__ __forceinline__ void ldsm4(uint32_t& r0, uint32_t& r1, uint32_t& r2, uint32_t& r3, uint32_t addr) {
    asm volatile("ldmatrix.sync.aligned.m8n8.x4.shared.b16 {%0,%1,%2,%3}, [%4];\n"
                 : "=r"(r0), "=r"(r1), "=r"(r2), "=r"(r3) : "r"(addr));
}
__device__ __forceinline__ void mma16816(float* d, const uint32_t* a, const uint32_t* b) {
    asm volatile("mma.sync.aligned.m16n8k16.row.col.f32.f16.f16.f32 "
                 "{%0,%1,%2,%3}, {%4,%5,%6,%7}, {%8,%9}, {%0,%1,%2,%3};\n"
                 : "+f"(d[0]), "+f"(d[1]), "+f"(d[2]), "+f"(d[3])
                 : "r"(a[0]), "r"(a[1]), "r"(a[2]), "r"(a[3]), "r"(b[0]), "r"(b[1]));
}

// ---------------- init ----------------
__global__ void init_flags() { g_nflag = 0; }

// ---------------- fp32 -> fp16 hi/lo split (optionally relu) ----------------
__global__ void split_rows(const float* __restrict__ src, __half* __restrict__ dh,
                           __half* __restrict__ dl, size_t n4, int relu) {
    size_t i = (size_t)blockIdx.x * 256 + threadIdx.x;
    if (i >= n4) return;
    float4 v = ((const float4*)src)[i];
    float vv[4] = {v.x, v.y, v.z, v.w};
    union { __half h[4]; uint2 u; } H, L;
#pragma unroll
    for (int j = 0; j < 4; j++) {
        float x = relu ? fmaxf(vv[j], 0.f) : vv[j];
        __half h = __float2half_rn(x);
        H.h[j] = h;
        L.h[j] = __float2half_rn(x - __half2float(h));
    }
    ((uint2*)dh)[i] = H.u;
    ((uint2*)dl)[i] = L.u;
}

// ---------------- fp32 [K][N] -> fp16 [N][K] transpose ----------------
__global__ void split_T(const float* __restrict__ src, __half* __restrict__ dh, int K, int N) {
    __shared__ float t[32][33];
    int bx = blockIdx.x, by = blockIdx.y;        // n block, k block
    int x = threadIdx.x, y = threadIdx.y;        // 32 x 8
#pragma unroll
    for (int i = 0; i < 32; i += 8)
        t[y + i][x] = src[(size_t)(by * 32 + y + i) * N + bx * 32 + x];
    __syncthreads();
#pragma unroll
    for (int i = 0; i < 32; i += 8)
        dh[(size_t)(bx * 32 + y + i) * K + by * 32 + x] = __float2half_rn(t[x][y + i]);
}

// ---------------- fp32 [K][N] -> fp32 [N][K] transpose (for fixup) ----------------
__global__ void transpose_f32(const float* __restrict__ src, float* __restrict__ dst, int K, int N) {
    __shared__ float t[32][33];
    int bx = blockIdx.x, by = blockIdx.y;
    int x = threadIdx.x, y = threadIdx.y;
#pragma unroll
    for (int i = 0; i < 32; i += 8)
        t[y + i][x] = src[(size_t)(by * 32 + y + i) * N + bx * 32 + x];
    __syncthreads();
#pragma unroll
    for (int i = 0; i < 32; i += 8)
        dst[(size_t)(bx * 32 + y + i) * K + by * 32 + x] = t[x][y + i];
}

// ---------------- rank-16 projection (exact fp32) ----------------
template<int RELU>
__global__ void lora_proj(const float* __restrict__ A, const float* __restrict__ Wl,
                          float* __restrict__ P, int K) {
    int row = blockIdx.x * 16 + (threadIdx.x >> 4);
    int r   = threadIdx.x & 15;
    const float* a = A + (size_t)row * K;
    float acc = 0.f;
    for (int k = 0; k < K; k += 4) {
        float4 av = *(const float4*)(a + k);
        if (RELU) {
            av.x = fmaxf(av.x, 0.f); av.y = fmaxf(av.y, 0.f);
            av.z = fmaxf(av.z, 0.f); av.w = fmaxf(av.w, 0.f);
        }
        acc += av.x * Wl[(k + 0) * 16 + r];
        acc += av.y * Wl[(k + 1) * 16 + r];
        acc += av.z * Wl[(k + 2) * 16 + r];
        acc += av.w * Wl[(k + 3) * 16 + r];
    }
    P[row * 16 + r] = acc;
}

// ---------------- fp16x2 tensor-core GEMM: Y = (Ah+Al)@Bh^T + L@Bm ----------------
// Ah/Al: [M][K] fp16 row-major; Bh: [N][K] fp16 row-major (K-major)
// L: [M][16] fp32; Bm: [16][N] fp32
__device__ __forceinline__ void frag_loadA(uint32_t a[2][4], uint32_t base, int warpM, int s, int lane) {
    int rlo = lane & 15;
    int c4  = s * 2 + (lane >> 4);
#pragma unroll
    for (int mi = 0; mi < 2; mi++) {
        int row = warpM + mi * 16 + rlo;
        uint32_t ad = base + row * 64 + ((c4 ^ ((row >> 1) & 3)) << 4);
        ldsm4(a[mi][0], a[mi][1], a[mi][2], a[mi][3], ad);
    }
}
__device__ __forceinline__ void frag_loadB(uint32_t b[8][2], uint32_t base, int warpN, int s, int lane) {
    int rlo = lane & 15;
    int c4  = s * 2 + (lane >> 4);
#pragma unroll
    for (int nj = 0; nj < 4; nj++) {
        int row = warpN + nj * 16 + rlo;
        uint32_t ad = base + row * 64 + ((c4 ^ ((row >> 1) & 3)) << 4);
        uint32_t r0, r1, r2, r3;
        ldsm4(r0, r1, r2, r3, ad);
        b[2 * nj][0] = r0; b[2 * nj][1] = r2;
        b[2 * nj + 1][0] = r1; b[2 * nj + 1][1] = r3;
    }
}
__device__ __forceinline__ void mma_all(float acc[2][8][4], uint32_t a[2][4], uint32_t b[8][2]) {
#pragma unroll
    for (int mi = 0; mi < 2; mi++)
#pragma unroll
        for (int ni = 0; ni < 8; ni++) mma16816(acc[mi][ni], a[mi], b[ni]);
}

#define STAGE_B 24576   // Ah 8K | Al 8K | Bh 8K

template<int SWAP>
__global__ void __launch_bounds__(256) gemm_f16x2(
    const __half* __restrict__ gAh, const __half* __restrict__ gAl,
    const __half* __restrict__ gBh,
    const float* __restrict__ gL, const float* __restrict__ gBm,
    float* __restrict__ Y, int M, int N, int K)
{
    extern __shared__ char smem[];
    const int tid = threadIdx.x, lane = tid & 31, wid = tid >> 5;
    const int m0 = (SWAP ? blockIdx.y : blockIdx.x) * 128;
    const int n0 = (SWAP ? blockIdx.x : blockIdx.y) * 128;
    const int warpM = (wid >> 1) * 32, warpN = (wid & 1) * 64;

    float acc[2][8][4];
#pragma unroll
    for (int mi = 0; mi < 2; mi++)
#pragma unroll
        for (int ni = 0; ni < 8; ni++)
#pragma unroll
            for (int q = 0; q < 4; q++) acc[mi][ni][q] = 0.f;

    const __half* srcs[3] = {gAh, gAl, gBh};

    auto stage_load = [&](int st, int k0) {
        char* base = smem + st * STAGE_B;
#pragma unroll
        for (int arr = 0; arr < 3; arr++) {
            int row0 = (arr < 2) ? m0 : n0;
            char* dst = base + arr * 8192;
#pragma unroll
            for (int i = 0; i < 2; i++) {
                int c = tid + i * 256;
                int row = c >> 2, c4 = c & 3;
                const __half* g = srcs[arr] + (size_t)(row0 + row) * K + k0 + c4 * 8;
                uint32_t d = (uint32_t)__cvta_generic_to_shared(
                    dst + row * 64 + ((c4 ^ ((row >> 1) & 3)) << 4));
                asm volatile("cp.async.cg.shared.global [%0], [%1], 16;\n" :: "r"(d), "l"(g));
            }
        }
        asm volatile("cp.async.commit_group;\n");
    };

    stage_load(0, 0);
    for (int k0 = 0; k0 < K; k0 += 32) {
        int cur = (k0 >> 5) & 1;
        if (k0 + 32 < K) {
            stage_load(cur ^ 1, k0 + 32);
            asm volatile("cp.async.wait_group 1;\n");
        } else {
            asm volatile("cp.async.wait_group 0;\n");
        }
        __syncthreads();
        uint32_t bS = (uint32_t)__cvta_generic_to_shared(smem + cur * STAGE_B);
        uint32_t bAh = bS, bAl = bS + 8192, bBh = bS + 16384;
#pragma unroll
        for (int s = 0; s < 2; s++) {
            uint32_t a[2][4], b[8][2];
            frag_loadB(b, bBh, warpN, s, lane);
            frag_loadA(a, bAh, warpM, s, lane);
            mma_all(acc, a, b);                       // Ah * Bh
            frag_loadA(a, bAl, warpM, s, lane);
            mma_all(acc, a, b);                       // Al * Bh
        }
        __syncthreads();
    }

    // ---------------- fp32 lora epilogue ----------------
    float* sL = (float*)smem;                  // [128][17]
    float* sB = (float*)(smem + 128 * 17 * 4); // [16][132]
    for (int i = tid; i < 128 * 16; i += 256) {
        int rw = i >> 4, rr = i & 15;
        sL[rw * 17 + rr] = gL[(size_t)(m0 + rw) * 16 + rr];
    }
    for (int i = tid; i < 16 * 128; i += 256) {
        int rr = i >> 7, cc = i & 127;
        sB[rr * 132 + cc] = gBm[(size_t)rr * N + n0 + cc];
    }
    __syncthreads();
    int r = lane >> 2, cb = (lane & 3) * 2;
#pragma unroll
    for (int rr = 0; rr < 16; rr++) {
        float L0 = sL[(warpM + r) * 17 + rr];
        float L1 = sL[(warpM + r + 8) * 17 + rr];
        float L2 = sL[(warpM + 16 + r) * 17 + rr];
        float L3 = sL[(warpM + 16 + r + 8) * 17 + rr];
#pragma unroll
        for (int ni = 0; ni < 8; ni++) {
            float b0v = sB[rr * 132 + warpN + ni * 8 + cb];
            float b1v = sB[rr * 132 + warpN + ni * 8 + cb + 1];
            acc[0][ni][0] += L0 * b0v; acc[0][ni][1] += L0 * b1v;
            acc[0][ni][2] += L1 * b0v; acc[0][ni][3] += L1 * b1v;
            acc[1][ni][0] += L2 * b0v; acc[1][ni][1] += L2 * b1v;
            acc[1][ni][2] += L3 * b0v; acc[1][ni][3] += L3 * b1v;
        }
    }
    // ---------------- writeback ----------------
#pragma unroll
    for (int mi = 0; mi < 2; mi++) {
        int row0 = m0 + warpM + mi * 16 + r;
#pragma unroll
        for (int ni = 0; ni < 8; ni++) {
            int col = n0 + warpN + ni * 8 + cb;
            *(float2*)&Y[(size_t)row0 * N + col]       = make_float2(acc[mi][ni][0], acc[mi][ni][1]);
            *(float2*)&Y[(size_t)(row0 + 8) * N + col] = make_float2(acc[mi][ni][2], acc[mi][ni][3]);
        }
    }
}

// ---------------- counts + near-zero flagging ----------------
__global__ void count_flag() {
    int c = blockIdx.x * 256 + threadIdx.x;
    int b = blockIdx.y;
    const float* p = g_y1 + (size_t)b * SEQ * ITR + c;
    int cnt = 0;
    for (int s = 0; s < SEQ; s++) {
        float v = p[(size_t)s * ITR];
        cnt += (v <= 0.f) ? 1 : 0;
        if (fabsf(v) < FIX_TAU) {
            int slot = atomicAdd(&g_nflag, 1);
            if (slot < FLAG_CAP) { g_flagm[slot] = b * SEQ + s; g_flagc[slot] = c; }
        }
    }
    g_counts[b * ITR + c] = cnt;
}

// ---------------- exact fp32 recompute of flagged elements (coalesced wT) ----------
__global__ void fixup(const float* __restrict__ x1, const float* __restrict__ wT,
                      const float* __restrict__ w_up_lb) {
    int warpId = (blockIdx.x * blockDim.x + threadIdx.x) >> 5;
    int lane = threadIdx.x & 31;
    int totalWarps = (gridDim.x * blockDim.x) >> 5;
    int n = min(g_nflag, FLAG_CAP);
    for (int i = warpId; i < n; i += totalWarps) {
        int m = g_flagm[i], c = g_flagc[i];
        const float* xr = x1 + (size_t)m * HID;
        const float* wc = wT + (size_t)c * HID;
        float s = 0.f;
        for (int k = lane * 4; k < HID; k += 128) {
            float4 xv = *(const float4*)(xr + k);
            float4 wv = *(const float4*)(wc + k);
            s += xv.x * wv.x + xv.y * wv.y + xv.z * wv.z + xv.w * wv.w;
        }
#pragma unroll
        for (int o = 16; o > 0; o >>= 1) s += __shfl_xor_sync(0xffffffffu, s, o);
        if (lane == 0) {
#pragma unroll
            for (int rr = 0; rr < 16; rr++) s += g_pup[m * 16 + rr] * w_up_lb[rr * ITR + c];
            float old = g_y1[(size_t)m * ITR + c];
            bool zo = (old <= 0.f), zn = (s <= 0.f);
            if (zo != zn) atomicAdd(&g_counts[(m >> 11) * ITR + c], zn ? 1 : -1);
            g_y1[(size_t)m * ITR + c] = s;
        }
    }
}

// ---------------- exact top-10 smallest (count, index) ----------------
__global__ void topk_kernel() {
    __shared__ int red[256];
    int b = blockIdx.x, tid = threadIdx.x;
    int prev = -1;
    for (int r = 0; r < KSAVE; r++) {
        int best = 0x7fffffff;
        for (int c = tid; c < ITR; c += 256) {
            int key = (g_counts[b * ITR + c] << 13) | c;
            if (key > prev && key < best) best = key;
        }
        red[tid] = best;
        __syncthreads();
        for (int s = 128; s > 0; s >>= 1) {
            if (tid < s) red[tid] = min(red[tid], red[tid + s]);
            __syncthreads();
        }
        prev = red[0];
        if (tid == 0) g_topk[b * KSAVE + r] = prev & 8191;
        __syncthreads();
    }
}

// ---------------- gather ----------------
__global__ void gather_save(float* __restrict__ outp) {
    int i = blockIdx.x * 256 + threadIdx.x;
    if (i >= NB * SEQ * KSAVE) return;
    int j = i % KSAVE;
    int s = (i / KSAVE) % SEQ;
    int b = i / (KSAVE * SEQ);
    int c = g_topk[b * KSAVE + j];
    float v = g_y1[(size_t)(b * SEQ + s) * ITR + c];
    outp[i] = fmaxf(v, 0.f);
}

// ---------------- launch ----------------
extern "C" void kernel_launch(void* const* d_in, const int* in_sizes, int n_in,
                              void* d_out, int out_size) {
    const float* x1      = (const float*)d_in[0];
    const float* w_up    = (const float*)d_in[1];
    const float* w_up_la = (const float*)d_in[2];
    const float* w_up_lb = (const float*)d_in[3];
    const float* w_down  = (const float*)d_in[4];
    const float* w_dn_la = (const float*)d_in[5];
    const float* w_dn_lb = (const float*)d_in[6];
    float* out = (float*)d_out;

    float *y1, *pup, *pdn, *wupT32;
    __half *x1h, *x1l, *wupT, *x2h, *x2l, *wdnT;
    cudaGetSymbolAddress((void**)&y1, g_y1);
    cudaGetSymbolAddress((void**)&pup, g_pup);
    cudaGetSymbolAddress((void**)&pdn, g_pdn);
    cudaGetSymbolAddress((void**)&x1h, g_x1h);
    cudaGetSymbolAddress((void**)&x1l, g_x1l);
    cudaGetSymbolAddress((void**)&wupT, g_wupT);
    cudaGetSymbolAddress((void**)&wupT32, g_wupT32);
    cudaGetSymbolAddress((void**)&x2h, g_x2h);
    cudaGetSymbolAddress((void**)&x2l, g_x2l);
    cudaGetSymbolAddress((void**)&wdnT, g_wdnT);

    cudaFuncSetAttribute(gemm_f16x2<0>, cudaFuncAttributeMaxDynamicSharedMemorySize, 2 * STAGE_B);
    cudaFuncSetAttribute(gemm_f16x2<1>, cudaFuncAttributeMaxDynamicSharedMemorySize, 2 * STAGE_B);

    init_flags<<<1, 1>>>();

    // ---- up projection ----
    lora_proj<0><<<MTOK / 16, 256>>>(x1, w_up_la, pup, HID);
    {
        size_t n4 = (size_t)MTOK * HID / 4;
        split_rows<<<(unsigned)((n4 + 255) / 256), 256>>>(x1, x1h, x1l, n4, 0);
    }
    split_T<<<dim3(ITR / 32, HID / 32), dim3(32, 8)>>>(w_up, wupT, HID, ITR);
    transpose_f32<<<dim3(ITR / 32, HID / 32), dim3(32, 8)>>>(w_up, wupT32, HID, ITR);
    gemm_f16x2<0><<<dim3(MTOK / 128, ITR / 128), 256, 2 * STAGE_B>>>(
        x1h, x1l, wupT, pup, w_up_lb, y1, MTOK, ITR, HID);

    // ---- selection path (exact) ----
    count_flag<<<dim3(ITR / 256, NB), 256>>>();
    fixup<<<512, 256>>>(x1, wupT32, w_up_lb);
    topk_kernel<<<NB, 256>>>();

    // ---- down projection ----
    lora_proj<1><<<MTOK / 16, 256>>>(y1, w_dn_la, pdn, ITR);
    {
        size_t n4 = (size_t)MTOK * ITR / 4;
        split_rows<<<(unsigned)((n4 + 255) / 256), 256>>>(y1, x2h, x2l, n4, 1);
    }
    split_T<<<dim3(HID / 32, ITR / 32), dim3(32, 8)>>>(w_down, wdnT, ITR, HID);
    gemm_f16x2<1><<<dim3(HID / 128, MTOK / 128), 256, 2 * STAGE_B>>>(
        x2h, x2l, wdnT, pdn, w_dn_lb, out, MTOK, HID, ITR);

    // ---- sparse save ----
    int save_elems = NB * SEQ * KSAVE;
    gather_save<<<(save_elems + 255) / 256, 256>>>(out + (out_size - save_elems));
}

// round 11
// speedup vs baseline: 3.3559x; 1.2996x over previous
#include <cuda_runtime.h>
#include <cuda_fp16.h>
#include <cstdint>

#define MTOK 8192
#define HID  2048
#define ITR  8192
#define NB   4
#define SEQ  2048
#define KSAVE 10
#define FLAG_CAP (1<<20)
#define FIX_TAU 3e-3f

// ---------------- device scratch ----------------
__device__ float  g_y1[(size_t)MTOK * ITR];        // raw up-proj (pre-relu), fixed up
__device__ __half g_x1h[(size_t)MTOK * HID];       // fp16 x1
__device__ __half g_wupT[(size_t)ITR * HID];       // fp16 [N][K]
__device__ float  g_wupT32[(size_t)ITR * HID];     // fp32 [N][K] for exact fixup
__device__ __half g_x2h[(size_t)MTOK * ITR];       // fp16 relu(y1), written by GEMM1 epilogue
__device__ __half g_wdnT[(size_t)HID * ITR];       // fp16 [N][K]
__device__ float g_pup[MTOK * 16];
__device__ float g_pdn[MTOK * 16];
__device__ int   g_counts[NB * ITR];
__device__ int   g_topk[NB * KSAVE];
__device__ int   g_nflag;
__device__ int   g_flagm[FLAG_CAP];
__device__ int   g_flagc[FLAG_CAP];

// ---------------- helpers ----------------
__device__ __forceinline__ void ldsm4(uint32_t& r0, uint32_t& r1, uint32_t& r2, uint32_t& r3, uint32_t addr) {
    asm volatile("ldmatrix.sync.aligned.m8n8.x4.shared.b16 {%0,%1,%2,%3}, [%4];\n"
                 : "=r"(r0), "=r"(r1), "=r"(r2), "=r"(r3) : "r"(addr));
}
__device__ __forceinline__ void mma16816(float* d, const uint32_t* a, const uint32_t* b) {
    asm volatile("mma.sync.aligned.m16n8k16.row.col.f32.f16.f16.f32 "
                 "{%0,%1,%2,%3}, {%4,%5,%6,%7}, {%8,%9}, {%0,%1,%2,%3};\n"
                 : "+f"(d[0]), "+f"(d[1]), "+f"(d[2]), "+f"(d[3])
                 : "r"(a[0]), "r"(a[1]), "r"(a[2]), "r"(a[3]), "r"(b[0]), "r"(b[1]));
}

// ---------------- init ----------------
__global__ void init_flags() { g_nflag = 0; }

// ---------------- fp32 -> fp16 ----------------
__global__ void to_half(const float* __restrict__ src, __half* __restrict__ dst, size_t n4) {
    size_t i = (size_t)blockIdx.x * 256 + threadIdx.x;
    if (i >= n4) return;
    float4 v = ((const float4*)src)[i];
    union { __half h[4]; uint2 u; } H;
    H.h[0] = __float2half_rn(v.x); H.h[1] = __float2half_rn(v.y);
    H.h[2] = __float2half_rn(v.z); H.h[3] = __float2half_rn(v.w);
    ((uint2*)dst)[i] = H.u;
}

// ---------------- fp32 [K][N] -> fp16 [N][K] transpose ----------------
__global__ void split_T(const float* __restrict__ src, __half* __restrict__ dh, int K, int N) {
    __shared__ float t[32][33];
    int bx = blockIdx.x, by = blockIdx.y;
    int x = threadIdx.x, y = threadIdx.y;   // 32 x 8
#pragma unroll
    for (int i = 0; i < 32; i += 8)
        t[y + i][x] = src[(size_t)(by * 32 + y + i) * N + bx * 32 + x];
    __syncthreads();
#pragma unroll
    for (int i = 0; i < 32; i += 8)
        dh[(size_t)(bx * 32 + y + i) * K + by * 32 + x] = __float2half_rn(t[x][y + i]);
}

// ---------------- fp32 [K][N] -> fp32 [N][K] transpose (for fixup) ----------------
__global__ void transpose_f32(const float* __restrict__ src, float* __restrict__ dst, int K, int N) {
    __shared__ float t[32][33];
    int bx = blockIdx.x, by = blockIdx.y;
    int x = threadIdx.x, y = threadIdx.y;
#pragma unroll
    for (int i = 0; i < 32; i += 8)
        t[y + i][x] = src[(size_t)(by * 32 + y + i) * N + bx * 32 + x];
    __syncthreads();
#pragma unroll
    for (int i = 0; i < 32; i += 8)
        dst[(size_t)(bx * 32 + y + i) * K + by * 32 + x] = t[x][y + i];
}

// ---------------- rank-16 projection from fp32 src (exact, for up-lora) -----------
__global__ void lora_proj_f(const float* __restrict__ A, const float* __restrict__ Wl,
                            float* __restrict__ P, int K) {
    int row = blockIdx.x * 16 + (threadIdx.x >> 4);
    int r   = threadIdx.x & 15;
    const float* a = A + (size_t)row * K;
    float acc = 0.f;
    for (int k = 0; k < K; k += 4) {
        float4 av = *(const float4*)(a + k);
        acc += av.x * Wl[(k + 0) * 16 + r];
        acc += av.y * Wl[(k + 1) * 16 + r];
        acc += av.z * Wl[(k + 2) * 16 + r];
        acc += av.w * Wl[(k + 3) * 16 + r];
    }
    P[row * 16 + r] = acc;
}

// ---------------- rank-16 projection from fp16 src (down-lora; relu pre-applied) --
__global__ void lora_proj_h(const __half* __restrict__ A, const float* __restrict__ Wl,
                            float* __restrict__ P, int K) {
    int row = blockIdx.x * 16 + (threadIdx.x >> 4);
    int r   = threadIdx.x & 15;
    const __half* a = A + (size_t)row * K;
    float acc = 0.f;
    for (int k = 0; k < K; k += 4) {
        __half2 h0 = *(const __half2*)(a + k);
        __half2 h1 = *(const __half2*)(a + k + 2);
        float2 f0 = __half22float2(h0);
        float2 f1 = __half22float2(h1);
        acc += f0.x * Wl[(k + 0) * 16 + r];
        acc += f0.y * Wl[(k + 1) * 16 + r];
        acc += f1.x * Wl[(k + 2) * 16 + r];
        acc += f1.y * Wl[(k + 3) * 16 + r];
    }
    P[row * 16 + r] = acc;
}

// ---------------- single-pass fp16 tensor-core GEMM: Y = A@B^T + L@Bm -------------
// A: [M][K] fp16 row-major; B: [N][K] fp16 row-major (K-major)
// L: [M][16] fp32; Bm: [16][N] fp32. If EPI: also write X2 = fp16 relu(Y).
__device__ __forceinline__ void frag_loadA(uint32_t a[2][4], uint32_t base, int warpM, int s, int lane) {
    int rlo = lane & 15;
    int c4  = s * 2 + (lane >> 4);
#pragma unroll
    for (int mi = 0; mi < 2; mi++) {
        int row = warpM + mi * 16 + rlo;
        uint32_t ad = base + row * 64 + ((c4 ^ ((row >> 1) & 3)) << 4);
        ldsm4(a[mi][0], a[mi][1], a[mi][2], a[mi][3], ad);
    }
}
__device__ __forceinline__ void frag_loadB(uint32_t b[8][2], uint32_t base, int warpN, int s, int lane) {
    int rlo = lane & 15;
    int c4  = s * 2 + (lane >> 4);
#pragma unroll
    for (int nj = 0; nj < 4; nj++) {
        int row = warpN + nj * 16 + rlo;
        uint32_t ad = base + row * 64 + ((c4 ^ ((row >> 1) & 3)) << 4);
        uint32_t r0, r1, r2, r3;
        ldsm4(r0, r1, r2, r3, ad);
        b[2 * nj][0] = r0; b[2 * nj][1] = r2;
        b[2 * nj + 1][0] = r1; b[2 * nj + 1][1] = r3;
    }
}

#define STAGE_B 16384   // A 8K | B 8K

template<int SWAP, int EPI>
__global__ void __launch_bounds__(256) gemm_f16(
    const __half* __restrict__ gA, const __half* __restrict__ gB,
    const float* __restrict__ gL, const float* __restrict__ gBm,
    float* __restrict__ Y, __half* __restrict__ X2, int M, int N, int K)
{
    extern __shared__ char smem[];
    const int tid = threadIdx.x, lane = tid & 31, wid = tid >> 5;
    const int m0 = (SWAP ? blockIdx.y : blockIdx.x) * 128;
    const int n0 = (SWAP ? blockIdx.x : blockIdx.y) * 128;
    const int warpM = (wid >> 1) * 32, warpN = (wid & 1) * 64;

    float acc[2][8][4];
#pragma unroll
    for (int mi = 0; mi < 2; mi++)
#pragma unroll
        for (int ni = 0; ni < 8; ni++)
#pragma unroll
            for (int q = 0; q < 4; q++) acc[mi][ni][q] = 0.f;

    const __half* srcs[2] = {gA, gB};

    auto stage_load = [&](int st, int k0) {
        char* base = smem + st * STAGE_B;
#pragma unroll
        for (int arr = 0; arr < 2; arr++) {
            int row0 = (arr == 0) ? m0 : n0;
            char* dst = base + arr * 8192;
#pragma unroll
            for (int i = 0; i < 2; i++) {
                int c = tid + i * 256;
                int row = c >> 2, c4 = c & 3;
                const __half* g = srcs[arr] + (size_t)(row0 + row) * K + k0 + c4 * 8;
                uint32_t d = (uint32_t)__cvta_generic_to_shared(
                    dst + row * 64 + ((c4 ^ ((row >> 1) & 3)) << 4));
                asm volatile("cp.async.cg.shared.global [%0], [%1], 16;\n" :: "r"(d), "l"(g));
            }
        }
        asm volatile("cp.async.commit_group;\n");
    };

    stage_load(0, 0);
    for (int k0 = 0; k0 < K; k0 += 32) {
        int cur = (k0 >> 5) & 1;
        if (k0 + 32 < K) {
            stage_load(cur ^ 1, k0 + 32);
            asm volatile("cp.async.wait_group 1;\n");
        } else {
            asm volatile("cp.async.wait_group 0;\n");
        }
        __syncthreads();
        uint32_t bS = (uint32_t)__cvta_generic_to_shared(smem + cur * STAGE_B);
#pragma unroll
        for (int s = 0; s < 2; s++) {
            uint32_t a[2][4], b[8][2];
            frag_loadB(b, bS + 8192, warpN, s, lane);
            frag_loadA(a, bS, warpM, s, lane);
#pragma unroll
            for (int mi = 0; mi < 2; mi++)
#pragma unroll
                for (int ni = 0; ni < 8; ni++) mma16816(acc[mi][ni], a[mi], b[ni]);
        }
        __syncthreads();
    }

    // ---------------- fp32 lora epilogue ----------------
    float* sL = (float*)smem;                  // [128][17]
    float* sB = (float*)(smem + 128 * 17 * 4); // [16][132]
    for (int i = tid; i < 128 * 16; i += 256) {
        int rw = i >> 4, rr = i & 15;
        sL[rw * 17 + rr] = gL[(size_t)(m0 + rw) * 16 + rr];
    }
    for (int i = tid; i < 16 * 128; i += 256) {
        int rr = i >> 7, cc = i & 127;
        sB[rr * 132 + cc] = gBm[(size_t)rr * N + n0 + cc];
    }
    __syncthreads();
    int r = lane >> 2, cb = (lane & 3) * 2;
#pragma unroll
    for (int rr = 0; rr < 16; rr++) {
        float L0 = sL[(warpM + r) * 17 + rr];
        float L1 = sL[(warpM + r + 8) * 17 + rr];
        float L2 = sL[(warpM + 16 + r) * 17 + rr];
        float L3 = sL[(warpM + 16 + r + 8) * 17 + rr];
#pragma unroll
        for (int ni = 0; ni < 8; ni++) {
            float b0v = sB[rr * 132 + warpN + ni * 8 + cb];
            float b1v = sB[rr * 132 + warpN + ni * 8 + cb + 1];
            acc[0][ni][0] += L0 * b0v; acc[0][ni][1] += L0 * b1v;
            acc[0][ni][2] += L1 * b0v; acc[0][ni][3] += L1 * b1v;
            acc[1][ni][0] += L2 * b0v; acc[1][ni][1] += L2 * b1v;
            acc[1][ni][2] += L3 * b0v; acc[1][ni][3] += L3 * b1v;
        }
    }
    // ---------------- writeback (+ optional fused relu->fp16 x2) ----------------
#pragma unroll
    for (int mi = 0; mi < 2; mi++) {
        int row0 = m0 + warpM + mi * 16 + r;
#pragma unroll
        for (int ni = 0; ni < 8; ni++) {
            int col = n0 + warpN + ni * 8 + cb;
            *(float2*)&Y[(size_t)row0 * N + col]       = make_float2(acc[mi][ni][0], acc[mi][ni][1]);
            *(float2*)&Y[(size_t)(row0 + 8) * N + col] = make_float2(acc[mi][ni][2], acc[mi][ni][3]);
            if (EPI) {
                __half2 h0 = __floats2half2_rn(fmaxf(acc[mi][ni][0], 0.f), fmaxf(acc[mi][ni][1], 0.f));
                __half2 h1 = __floats2half2_rn(fmaxf(acc[mi][ni][2], 0.f), fmaxf(acc[mi][ni][3], 0.f));
                *(__half2*)&X2[(size_t)row0 * N + col]       = h0;
                *(__half2*)&X2[(size_t)(row0 + 8) * N + col] = h1;
            }
        }
    }
}

// ---------------- counts + near-zero flagging ----------------
__global__ void count_flag() {
    int c = blockIdx.x * 256 + threadIdx.x;
    int b = blockIdx.y;
    const float* p = g_y1 + (size_t)b * SEQ * ITR + c;
    int cnt = 0;
    for (int s = 0; s < SEQ; s++) {
        float v = p[(size_t)s * ITR];
        cnt += (v <= 0.f) ? 1 : 0;
        if (fabsf(v) < FIX_TAU) {
            int slot = atomicAdd(&g_nflag, 1);
            if (slot < FLAG_CAP) { g_flagm[slot] = b * SEQ + s; g_flagc[slot] = c; }
        }
    }
    g_counts[b * ITR + c] = cnt;
}

// ---------------- exact fp32 recompute of flagged elements (coalesced wT) ----------
__global__ void fixup(const float* __restrict__ x1, const float* __restrict__ wT,
                      const float* __restrict__ w_up_lb) {
    int warpId = (blockIdx.x * blockDim.x + threadIdx.x) >> 5;
    int lane = threadIdx.x & 31;
    int totalWarps = (gridDim.x * blockDim.x) >> 5;
    int n = min(g_nflag, FLAG_CAP);
    for (int i = warpId; i < n; i += totalWarps) {
        int m = g_flagm[i], c = g_flagc[i];
        const float* xr = x1 + (size_t)m * HID;
        const float* wc = wT + (size_t)c * HID;
        float s = 0.f;
        for (int k = lane * 4; k < HID; k += 128) {
            float4 xv = *(const float4*)(xr + k);
            float4 wv = *(const float4*)(wc + k);
            s += xv.x * wv.x + xv.y * wv.y + xv.z * wv.z + xv.w * wv.w;
        }
#pragma unroll
        for (int o = 16; o > 0; o >>= 1) s += __shfl_xor_sync(0xffffffffu, s, o);
        if (lane == 0) {
#pragma unroll
            for (int rr = 0; rr < 16; rr++) s += g_pup[m * 16 + rr] * w_up_lb[rr * ITR + c];
            float old = g_y1[(size_t)m * ITR + c];
            bool zo = (old <= 0.f), zn = (s <= 0.f);
            if (zo != zn) atomicAdd(&g_counts[(m >> 11) * ITR + c], zn ? 1 : -1);
            g_y1[(size_t)m * ITR + c] = s;
        }
    }
}

// ---------------- exact top-10 smallest (count, index) ----------------
__global__ void topk_kernel() {
    __shared__ int red[256];
    int b = blockIdx.x, tid = threadIdx.x;
    int prev = -1;
    for (int r = 0; r < KSAVE; r++) {
        int best = 0x7fffffff;
        for (int c = tid; c < ITR; c += 256) {
            int key = (g_counts[b * ITR + c] << 13) | c;
            if (key > prev && key < best) best = key;
        }
        red[tid] = best;
        __syncthreads();
        for (int s = 128; s > 0; s >>= 1) {
            if (tid < s) red[tid] = min(red[tid], red[tid + s]);
            __syncthreads();
        }
        prev = red[0];
        if (tid == 0) g_topk[b * KSAVE + r] = prev & 8191;
        __syncthreads();
    }
}

// ---------------- gather ----------------
__global__ void gather_save(float* __restrict__ outp) {
    int i = blockIdx.x * 256 + threadIdx.x;
    if (i >= NB * SEQ * KSAVE) return;
    int j = i % KSAVE;
    int s = (i / KSAVE) % SEQ;
    int b = i / (KSAVE * SEQ);
    int c = g_topk[b * KSAVE + j];
    float v = g_y1[(size_t)(b * SEQ + s) * ITR + c];
    outp[i] = fmaxf(v, 0.f);
}

// ---------------- launch ----------------
extern "C" void kernel_launch(void* const* d_in, const int* in_sizes, int n_in,
                              void* d_out, int out_size) {
    const float* x1      = (const float*)d_in[0];
    const float* w_up    = (const float*)d_in[1];
    const float* w_up_la = (const float*)d_in[2];
    const float* w_up_lb = (const float*)d_in[3];
    const float* w_down  = (const float*)d_in[4];
    const float* w_dn_la = (const float*)d_in[5];
    const float* w_dn_lb = (const float*)d_in[6];
    float* out = (float*)d_out;

    float *y1, *pup, *pdn, *wupT32;
    __half *x1h, *wupT, *x2h, *wdnT;
    cudaGetSymbolAddress((void**)&y1, g_y1);
    cudaGetSymbolAddress((void**)&pup, g_pup);
    cudaGetSymbolAddress((void**)&pdn, g_pdn);
    cudaGetSymbolAddress((void**)&x1h, g_x1h);
    cudaGetSymbolAddress((void**)&wupT, g_wupT);
    cudaGetSymbolAddress((void**)&wupT32, g_wupT32);
    cudaGetSymbolAddress((void**)&x2h, g_x2h);
    cudaGetSymbolAddress((void**)&wdnT, g_wdnT);

    cudaFuncSetAttribute(gemm_f16<0, 1>, cudaFuncAttributeMaxDynamicSharedMemorySize, 2 * STAGE_B);
    cudaFuncSetAttribute(gemm_f16<1, 0>, cudaFuncAttributeMaxDynamicSharedMemorySize, 2 * STAGE_B);

    init_flags<<<1, 1>>>();

    // ---- up projection (fused: y1 fp32 + x2h fp16-relu in one epilogue) ----
    lora_proj_f<<<MTOK / 16, 256>>>(x1, w_up_la, pup, HID);
    {
        size_t n4 = (size_t)MTOK * HID / 4;
        to_half<<<(unsigned)((n4 + 255) / 256), 256>>>(x1, x1h, n4);
    }
    split_T<<<dim3(ITR / 32, HID / 32), dim3(32, 8)>>>(w_up, wupT, HID, ITR);
    transpose_f32<<<dim3(ITR / 32, HID / 32), dim3(32, 8)>>>(w_up, wupT32, HID, ITR);
    gemm_f16<0, 1><<<dim3(MTOK / 128, ITR / 128), 256, 2 * STAGE_B>>>(
        x1h, wupT, pup, w_up_lb, y1, x2h, MTOK, ITR, HID);

    // ---- selection path (exact) ----
    count_flag<<<dim3(ITR / 256, NB), 256>>>();
    fixup<<<512, 256>>>(x1, wupT32, w_up_lb);
    topk_kernel<<<NB, 256>>>();

    // ---- down projection ----
    lora_proj_h<<<MTOK / 16, 256>>>(x2h, w_dn_la, pdn, ITR);
    split_T<<<dim3(HID / 32, ITR / 32), dim3(32, 8)>>>(w_down, wdnT, ITR, HID);
    gemm_f16<1, 0><<<dim3(HID / 128, MTOK / 128), 256, 2 * STAGE_B>>>(
        x2h, wdnT, pdn, w_dn_lb, out, (half*)nullptr, MTOK, HID, ITR);

    // ---- sparse save ----
    int save_elems = NB * SEQ * KSAVE;
    gather_save<<<(save_elems + 255) / 256, 256>>>(out + (out_size - save_elems));
}

// round 12
// speedup vs baseline: 4.1984x; 1.2511x over previous
#include <cuda_runtime.h>
#include <cuda_fp16.h>
#include <cstdint>

#define MTOK 8192
#define HID  2048
#define ITR  8192
#define NB   4
#define SEQ  2048
#define KSAVE 10
#define FLAG_CAP (1<<20)
#define FIX_TAU 3e-3f

#define BM 128
#define BN 256
#define BK 32
#define ASTG (BM*BK*2)
#define BSTG (BN*BK*2)
#define STG  (ASTG+BSTG)     // 24576
#define DSMEM (2*STG)        // 49152

// ---------------- device scratch ----------------
__device__ __half g_x1h[(size_t)MTOK * HID];
__device__ __half g_wupT[(size_t)ITR * HID];       // fp16 [N][K]
__device__ float  g_wupT32[(size_t)ITR * HID];     // fp32 [N][K] for exact fixup
__device__ __half g_x2h[(size_t)MTOK * ITR];       // fp16 relu(y1)
__device__ __half g_wdnT[(size_t)HID * ITR];       // fp16 [N][K]
__device__ float g_pup[MTOK * 16];
__device__ float g_pdn[MTOK * 16];
__device__ int   g_counts[NB * ITR];
__device__ int   g_topk[NB * KSAVE];
__device__ int   g_nflag;
__device__ int   g_flagm[FLAG_CAP];
__device__ int   g_flagc[FLAG_CAP];

// ---------------- helpers ----------------
__device__ __forceinline__ void ldsm4(uint32_t& r0, uint32_t& r1, uint32_t& r2, uint32_t& r3, uint32_t addr) {
    asm volatile("ldmatrix.sync.aligned.m8n8.x4.shared.b16 {%0,%1,%2,%3}, [%4];\n"
                 : "=r"(r0), "=r"(r1), "=r"(r2), "=r"(r3) : "r"(addr));
}
__device__ __forceinline__ void mma16816(float* d, const uint32_t* a, const uint32_t* b) {
    asm volatile("mma.sync.aligned.m16n8k16.row.col.f32.f16.f16.f32 "
                 "{%0,%1,%2,%3}, {%4,%5,%6,%7}, {%8,%9}, {%0,%1,%2,%3};\n"
                 : "+f"(d[0]), "+f"(d[1]), "+f"(d[2]), "+f"(d[3])
                 : "r"(a[0]), "r"(a[1]), "r"(a[2]), "r"(a[3]), "r"(b[0]), "r"(b[1]));
}

// ---------------- init: zero counts, pdn, nflag ----------------
__global__ void init_zero() {
    int i = blockIdx.x * 256 + threadIdx.x;
    if (i == 0) g_nflag = 0;
    if (i < NB * ITR) g_counts[i] = 0;
    if (i < MTOK * 16) g_pdn[i] = 0.f;
}

// ---------------- fp32 -> fp16 ----------------
__global__ void to_half(const float* __restrict__ src, __half* __restrict__ dst, size_t n4) {
    size_t i = (size_t)blockIdx.x * 256 + threadIdx.x;
    if (i >= n4) return;
    float4 v = ((const float4*)src)[i];
    union { __half h[4]; uint2 u; } H;
    H.h[0] = __float2half_rn(v.x); H.h[1] = __float2half_rn(v.y);
    H.h[2] = __float2half_rn(v.z); H.h[3] = __float2half_rn(v.w);
    ((uint2*)dst)[i] = H.u;
}

// ---------------- fp32 [K][N] -> fp16 [N][K] transpose ----------------
__global__ void split_T(const float* __restrict__ src, __half* __restrict__ dh, int K, int N) {
    __shared__ float t[32][33];
    int bx = blockIdx.x, by = blockIdx.y;
    int x = threadIdx.x, y = threadIdx.y;   // 32 x 8
#pragma unroll
    for (int i = 0; i < 32; i += 8)
        t[y + i][x] = src[(size_t)(by * 32 + y + i) * N + bx * 32 + x];
    __syncthreads();
#pragma unroll
    for (int i = 0; i < 32; i += 8)
        dh[(size_t)(bx * 32 + y + i) * K + by * 32 + x] = __float2half_rn(t[x][y + i]);
}

// ---------------- fp32 [K][N] -> fp32 [N][K] transpose ----------------
__global__ void transpose_f32(const float* __restrict__ src, float* __restrict__ dst, int K, int N) {
    __shared__ float t[32][33];
    int bx = blockIdx.x, by = blockIdx.y;
    int x = threadIdx.x, y = threadIdx.y;
#pragma unroll
    for (int i = 0; i < 32; i += 8)
        t[y + i][x] = src[(size_t)(by * 32 + y + i) * N + bx * 32 + x];
    __syncthreads();
#pragma unroll
    for (int i = 0; i < 32; i += 8)
        dst[(size_t)(bx * 32 + y + i) * K + by * 32 + x] = t[x][y + i];
}

// ---------------- rank-16 up-lora projection (exact fp32) ----------------
__global__ void lora_proj_f(const float* __restrict__ A, const float* __restrict__ Wl,
                            float* __restrict__ P, int K) {
    int row = blockIdx.x * 16 + (threadIdx.x >> 4);
    int r   = threadIdx.x & 15;
    const float* a = A + (size_t)row * K;
    float acc = 0.f;
    for (int k = 0; k < K; k += 4) {
        float4 av = *(const float4*)(a + k);
        acc += av.x * Wl[(k + 0) * 16 + r];
        acc += av.y * Wl[(k + 1) * 16 + r];
        acc += av.z * Wl[(k + 2) * 16 + r];
        acc += av.w * Wl[(k + 3) * 16 + r];
    }
    P[row * 16 + r] = acc;
}

// ---------------- fused fp16 GEMM 128x256 ----------------
// Y = A@B^T + L@Bm.  EPI=1 (up-proj): write x2h=relu fp16, count sign<=-tau,
// flag |v|<tau, accumulate pdn += relu(v)*Wdl.  EPI=0: write fp32 Y.
template<int SWAP, int EPI>
__global__ void __launch_bounds__(256, 1) gemm_f16(
    const __half* __restrict__ gA, const __half* __restrict__ gB,
    const float* __restrict__ gL, const float* __restrict__ gBm,
    const float* __restrict__ gWdl,
    float* __restrict__ Y, __half* __restrict__ X2, int M, int N, int K)
{
    extern __shared__ char smem[];
    const int tid = threadIdx.x, lane = tid & 31, wid = tid >> 5;
    const int m0 = (SWAP ? blockIdx.y : blockIdx.x) * BM;
    const int n0 = (SWAP ? blockIdx.x : blockIdx.y) * BN;
    const int warpM = (wid >> 2) * 64, warpN = (wid & 3) * 64;

    float acc[4][8][4];
#pragma unroll
    for (int mi = 0; mi < 4; mi++)
#pragma unroll
        for (int ni = 0; ni < 8; ni++)
#pragma unroll
            for (int q = 0; q < 4; q++) acc[mi][ni][q] = 0.f;

    auto stage_load = [&](int st, int k0) {
        char* base = smem + st * STG;
#pragma unroll
        for (int i = 0; i < 2; i++) {          // A: 8KB
            int c = tid + i * 256;
            int row = c >> 2, c4 = c & 3;
            const __half* g = gA + (size_t)(m0 + row) * K + k0 + c4 * 8;
            uint32_t d = (uint32_t)__cvta_generic_to_shared(
                base + row * 64 + ((c4 ^ ((row >> 1) & 3)) << 4));
            asm volatile("cp.async.cg.shared.global [%0], [%1], 16;\n" :: "r"(d), "l"(g));
        }
#pragma unroll
        for (int i = 0; i < 4; i++) {          // B: 16KB
            int c = tid + i * 256;
            int row = c >> 2, c4 = c & 3;
            const __half* g = gB + (size_t)(n0 + row) * K + k0 + c4 * 8;
            uint32_t d = (uint32_t)__cvta_generic_to_shared(
                base + ASTG + row * 64 + ((c4 ^ ((row >> 1) & 3)) << 4));
            asm volatile("cp.async.cg.shared.global [%0], [%1], 16;\n" :: "r"(d), "l"(g));
        }
        asm volatile("cp.async.commit_group;\n");
    };

    stage_load(0, 0);
    const int rlo = lane & 15;
    for (int k0 = 0; k0 < K; k0 += BK) {
        int cur = (k0 / BK) & 1;
        if (k0 + BK < K) {
            stage_load(cur ^ 1, k0 + BK);
            asm volatile("cp.async.wait_group 1;\n");
        } else {
            asm volatile("cp.async.wait_group 0;\n");
        }
        __syncthreads();
        uint32_t bA = (uint32_t)__cvta_generic_to_shared(smem + cur * STG);
        uint32_t bB = bA + ASTG;
#pragma unroll
        for (int s = 0; s < 2; s++) {
            int c4 = s * 2 + (lane >> 4);
            uint32_t a[4][4], b[8][2];
#pragma unroll
            for (int nj = 0; nj < 4; nj++) {
                int row = warpN + nj * 16 + rlo;
                uint32_t r0, r1, r2, r3;
                ldsm4(r0, r1, r2, r3, bB + row * 64 + ((c4 ^ ((row >> 1) & 3)) << 4));
                b[2 * nj][0] = r0; b[2 * nj][1] = r2;
                b[2 * nj + 1][0] = r1; b[2 * nj + 1][1] = r3;
            }
#pragma unroll
            for (int mi = 0; mi < 4; mi++) {
                int row = warpM + mi * 16 + rlo;
                ldsm4(a[mi][0], a[mi][1], a[mi][2], a[mi][3],
                      bA + row * 64 + ((c4 ^ ((row >> 1) & 3)) << 4));
            }
#pragma unroll
            for (int mi = 0; mi < 4; mi++)
#pragma unroll
                for (int ni = 0; ni < 8; ni++) mma16816(acc[mi][ni], a[mi], b[ni]);
        }
        __syncthreads();
    }

    // ---------------- epilogue: lora add (+ pdn/count/flag for EPI) ----------------
    float* sL   = (float*)smem;                       // [128][17]  8704B
    float* sB16 = (float*)(smem + 8704);              // [16][260] 16640B
    float* sWdl = (float*)(smem + 8704 + 16640);      // [256][17] 17408B (EPI only)
    for (int i = tid; i < BM * 16; i += 256) {
        int rw = i >> 4, rr = i & 15;
        sL[rw * 17 + rr] = gL[(size_t)(m0 + rw) * 16 + rr];
    }
    for (int i = tid; i < 16 * BN; i += 256) {
        int rr = i >> 8, cc = i & 255;
        sB16[rr * 260 + cc] = gBm[(size_t)rr * N + n0 + cc];
    }
    if (EPI) {
        for (int i = tid; i < BN * 16; i += 256) {
            int cc = i >> 4, rr = i & 15;
            sWdl[cc * 17 + rr] = gWdl[(size_t)(n0 + cc) * 16 + rr];
        }
    }
    __syncthreads();
    const int r = lane >> 2, cb = (lane & 3) * 2;
#pragma unroll
    for (int rr = 0; rr < 16; rr++) {
        float Lv[8];
#pragma unroll
        for (int mi = 0; mi < 4; mi++) {
            Lv[2 * mi]     = sL[(warpM + mi * 16 + r) * 17 + rr];
            Lv[2 * mi + 1] = sL[(warpM + mi * 16 + r + 8) * 17 + rr];
        }
#pragma unroll
        for (int ni = 0; ni < 8; ni++) {
            float b0v = sB16[rr * 260 + warpN + ni * 8 + cb];
            float b1v = sB16[rr * 260 + warpN + ni * 8 + cb + 1];
#pragma unroll
            for (int mi = 0; mi < 4; mi++) {
                acc[mi][ni][0] += Lv[2 * mi] * b0v;     acc[mi][ni][1] += Lv[2 * mi] * b1v;
                acc[mi][ni][2] += Lv[2 * mi + 1] * b0v; acc[mi][ni][3] += Lv[2 * mi + 1] * b1v;
            }
        }
    }

    if (EPI) {
        // counts: #(acc <= -tau) per column; flagged band handled by fixup
        int bidx = m0 >> 11;
#pragma unroll
        for (int ni = 0; ni < 8; ni++) {
            int c0 = 0, c1 = 0;
#pragma unroll
            for (int mi = 0; mi < 4; mi++) {
                c0 += (acc[mi][ni][0] <= -FIX_TAU) + (acc[mi][ni][2] <= -FIX_TAU);
                c1 += (acc[mi][ni][1] <= -FIX_TAU) + (acc[mi][ni][3] <= -FIX_TAU);
            }
            int packed = c0 | (c1 << 16);
            packed += __shfl_xor_sync(0xffffffffu, packed, 4);
            packed += __shfl_xor_sync(0xffffffffu, packed, 8);
            packed += __shfl_xor_sync(0xffffffffu, packed, 16);
            if (r == 0) {
                int col = n0 + warpN + ni * 8 + cb;
                atomicAdd(&g_counts[bidx * ITR + col], packed & 0xffff);
                atomicAdd(&g_counts[bidx * ITR + col + 1], packed >> 16);
            }
        }
        // pdn[m][rr] += sum_col relu(acc)*Wdl[col][rr]
#pragma unroll
        for (int rr = 0; rr < 16; rr++) {
            float s[8];
#pragma unroll
            for (int j = 0; j < 8; j++) s[j] = 0.f;
#pragma unroll
            for (int ni = 0; ni < 8; ni++) {
                float w0 = sWdl[(warpN + ni * 8 + cb) * 17 + rr];
                float w1 = sWdl[(warpN + ni * 8 + cb + 1) * 17 + rr];
#pragma unroll
                for (int mi = 0; mi < 4; mi++) {
                    s[2 * mi]     += fmaxf(acc[mi][ni][0], 0.f) * w0 + fmaxf(acc[mi][ni][1], 0.f) * w1;
                    s[2 * mi + 1] += fmaxf(acc[mi][ni][2], 0.f) * w0 + fmaxf(acc[mi][ni][3], 0.f) * w1;
                }
            }
#pragma unroll
            for (int j = 0; j < 8; j++) {
                s[j] += __shfl_xor_sync(0xffffffffu, s[j], 1);
                s[j] += __shfl_xor_sync(0xffffffffu, s[j], 2);
            }
            if ((lane & 3) == 0) {
#pragma unroll
                for (int mi = 0; mi < 4; mi++) {
                    atomicAdd(&g_pdn[(m0 + warpM + mi * 16 + r) * 16 + rr], s[2 * mi]);
                    atomicAdd(&g_pdn[(m0 + warpM + mi * 16 + r + 8) * 16 + rr], s[2 * mi + 1]);
                }
            }
        }
    }

    // ---------------- writeback ----------------
#pragma unroll
    for (int mi = 0; mi < 4; mi++) {
        int row0 = m0 + warpM + mi * 16 + r;
#pragma unroll
        for (int ni = 0; ni < 8; ni++) {
            int col = n0 + warpN + ni * 8 + cb;
            if (EPI) {
                __half2 h0 = __floats2half2_rn(fmaxf(acc[mi][ni][0], 0.f), fmaxf(acc[mi][ni][1], 0.f));
                __half2 h1 = __floats2half2_rn(fmaxf(acc[mi][ni][2], 0.f), fmaxf(acc[mi][ni][3], 0.f));
                *(__half2*)&X2[(size_t)row0 * N + col]       = h0;
                *(__half2*)&X2[(size_t)(row0 + 8) * N + col] = h1;
                // flag |v| < tau (warp-aggregated)
#pragma unroll
                for (int q = 0; q < 4; q++) {
                    bool t = fabsf(acc[mi][ni][q]) < FIX_TAU;
                    unsigned msk = __ballot_sync(0xffffffffu, t);
                    if (msk) {
                        int ldr = __ffs(msk) - 1;
                        int base = 0;
                        if (lane == ldr) base = atomicAdd(&g_nflag, __popc(msk));
                        base = __shfl_sync(0xffffffffu, base, ldr);
                        if (t) {
                            int off = base + __popc(msk & ((1u << lane) - 1));
                            if (off < FLAG_CAP) {
                                g_flagm[off] = row0 + ((q >= 2) ? 8 : 0);
                                g_flagc[off] = col + (q & 1);
                            }
                        }
                    }
                }
            } else {
                *(float2*)&Y[(size_t)row0 * N + col]       = make_float2(acc[mi][ni][0], acc[mi][ni][1]);
                *(float2*)&Y[(size_t)(row0 + 8) * N + col] = make_float2(acc[mi][ni][2], acc[mi][ni][3]);
            }
        }
    }
}

// ---------------- exact fp32 recompute of flagged elements ----------------
__global__ void fixup(const float* __restrict__ x1, const float* __restrict__ wT,
                      const float* __restrict__ w_up_lb) {
    int warpId = (blockIdx.x * blockDim.x + threadIdx.x) >> 5;
    int lane = threadIdx.x & 31;
    int totalWarps = (gridDim.x * blockDim.x) >> 5;
    int n = min(g_nflag, FLAG_CAP);
    for (int i = warpId; i < n; i += totalWarps) {
        int m = g_flagm[i], c = g_flagc[i];
        const float* xr = x1 + (size_t)m * HID;
        const float* wc = wT + (size_t)c * HID;
        float s = 0.f;
        for (int k = lane * 4; k < HID; k += 128) {
            float4 xv = *(const float4*)(xr + k);
            float4 wv = *(const float4*)(wc + k);
            s += xv.x * wv.x + xv.y * wv.y + xv.z * wv.z + xv.w * wv.w;
        }
#pragma unroll
        for (int o = 16; o > 0; o >>= 1) s += __shfl_xor_sync(0xffffffffu, s, o);
        if (lane == 0) {
#pragma unroll
            for (int rr = 0; rr < 16; rr++) s += g_pup[m * 16 + rr] * w_up_lb[rr * ITR + c];
            if (s <= 0.f) atomicAdd(&g_counts[(m >> 11) * ITR + c], 1);
            g_x2h[(size_t)m * ITR + c] = __float2half_rn(fmaxf(s, 0.f));
        }
    }
}

// ---------------- exact top-10 smallest (count, index) ----------------
__global__ void topk_kernel() {
    __shared__ int red[256];
    int b = blockIdx.x, tid = threadIdx.x;
    int prev = -1;
    for (int r = 0; r < KSAVE; r++) {
        int best = 0x7fffffff;
        for (int c = tid; c < ITR; c += 256) {
            int key = (g_counts[b * ITR + c] << 13) | c;
            if (key > prev && key < best) best = key;
        }
        red[tid] = best;
        __syncthreads();
        for (int s = 128; s > 0; s >>= 1) {
            if (tid < s) red[tid] = min(red[tid], red[tid + s]);
            __syncthreads();
        }
        prev = red[0];
        if (tid == 0) g_topk[b * KSAVE + r] = prev & 8191;
        __syncthreads();
    }
}

// ---------------- gather ----------------
__global__ void gather_save(float* __restrict__ outp) {
    int i = blockIdx.x * 256 + threadIdx.x;
    if (i >= NB * SEQ * KSAVE) return;
    int j = i % KSAVE;
    int s = (i / KSAVE) % SEQ;
    int b = i / (KSAVE * SEQ);
    int c = g_topk[b * KSAVE + j];
    outp[i] = __half2float(g_x2h[(size_t)(b * SEQ + s) * ITR + c]);
}

// ---------------- launch ----------------
extern "C" void kernel_launch(void* const* d_in, const int* in_sizes, int n_in,
                              void* d_out, int out_size) {
    const float* x1      = (const float*)d_in[0];
    const float* w_up    = (const float*)d_in[1];
    const float* w_up_la = (const float*)d_in[2];
    const float* w_up_lb = (const float*)d_in[3];
    const float* w_down  = (const float*)d_in[4];
    const float* w_dn_la = (const float*)d_in[5];
    const float* w_dn_lb = (const float*)d_in[6];
    float* out = (float*)d_out;

    float *pup, *wupT32;
    __half *x1h, *wupT, *x2h, *wdnT;
    float *pdn;
    cudaGetSymbolAddress((void**)&pup, g_pup);
    cudaGetSymbolAddress((void**)&pdn, g_pdn);
    cudaGetSymbolAddress((void**)&x1h, g_x1h);
    cudaGetSymbolAddress((void**)&wupT, g_wupT);
    cudaGetSymbolAddress((void**)&wupT32, g_wupT32);
    cudaGetSymbolAddress((void**)&x2h, g_x2h);
    cudaGetSymbolAddress((void**)&wdnT, g_wdnT);

    cudaFuncSetAttribute(gemm_f16<0, 1>, cudaFuncAttributeMaxDynamicSharedMemorySize, DSMEM);
    cudaFuncSetAttribute(gemm_f16<1, 0>, cudaFuncAttributeMaxDynamicSharedMemorySize, DSMEM);

    init_zero<<<(MTOK * 16 + 255) / 256, 256>>>();

    // ---- up projection (fused epilogue: x2h + counts + flags + pdn) ----
    lora_proj_f<<<MTOK / 16, 256>>>(x1, w_up_la, pup, HID);
    {
        size_t n4 = (size_t)MTOK * HID / 4;
        to_half<<<(unsigned)((n4 + 255) / 256), 256>>>(x1, x1h, n4);
    }
    split_T<<<dim3(ITR / 32, HID / 32), dim3(32, 8)>>>(w_up, wupT, HID, ITR);
    transpose_f32<<<dim3(ITR / 32, HID / 32), dim3(32, 8)>>>(w_up, wupT32, HID, ITR);
    gemm_f16<0, 1><<<dim3(MTOK / BM, ITR / BN), 256, DSMEM>>>(
        x1h, wupT, pup, w_up_lb, w_dn_la, (float*)nullptr, x2h, MTOK, ITR, HID);

    // ---- selection path (exact) ----
    fixup<<<512, 256>>>(x1, wupT32, w_up_lb);
    topk_kernel<<<NB, 256>>>();

    // ---- down projection ----
    split_T<<<dim3(HID / 32, ITR / 32), dim3(32, 8)>>>(w_down, wdnT, ITR, HID);
    gemm_f16<1, 0><<<dim3(HID / BN, MTOK / BM), 256, DSMEM>>>(
        x2h, wdnT, pdn, w_dn_lb, (float*)nullptr, out, (__half*)nullptr, MTOK, HID, ITR);

    // ---- sparse save ----
    int save_elems = NB * SEQ * KSAVE;
    gather_save<<<(save_elems + 255) / 256, 256>>>(out + (out_size - save_elems));
}

// round 13
// speedup vs baseline: 4.2831x; 1.0202x over previous
#include <cuda_runtime.h>
#include <cuda_fp16.h>
#include <cstdint>

#define MTOK 8192
#define HID  2048
#define ITR  8192
#define NB   4
#define SEQ  2048
#define KSAVE 10
#define FLAG_CAP (1<<20)
#define FIX_TAU 2e-3f

#define BM 128
#define BN 256
#define BK 32
#define ASTG (BM*BK*2)
#define BSTG (BN*BK*2)
#define STG  (ASTG+BSTG)     // 24576
#define NSTAGE 3
#define DSMEM (NSTAGE*STG)   // 73728

// ---------------- device scratch ----------------
__device__ __half g_x1h[(size_t)MTOK * HID];
__device__ __half g_wupT[(size_t)ITR * HID];       // fp16 [N][K]
__device__ float  g_wupT32[(size_t)ITR * HID];     // fp32 [N][K] for exact fixup
__device__ __half g_x2h[(size_t)MTOK * ITR];       // fp16 relu(y1)
__device__ __half g_wdnT[(size_t)HID * ITR];       // fp16 [N][K]
__device__ float g_pup[MTOK * 16];
__device__ float g_pdn[MTOK * 16];
__device__ int   g_counts[NB * ITR];
__device__ int   g_topk[NB * KSAVE];
__device__ int   g_nflag;
__device__ int   g_flagm[FLAG_CAP];
__device__ int   g_flagc[FLAG_CAP];

// ---------------- helpers ----------------
__device__ __forceinline__ void ldsm4(uint32_t& r0, uint32_t& r1, uint32_t& r2, uint32_t& r3, uint32_t addr) {
    asm volatile("ldmatrix.sync.aligned.m8n8.x4.shared.b16 {%0,%1,%2,%3}, [%4];\n"
                 : "=r"(r0), "=r"(r1), "=r"(r2), "=r"(r3) : "r"(addr));
}
__device__ __forceinline__ void mma16816(float* d, const uint32_t* a, const uint32_t* b) {
    asm volatile("mma.sync.aligned.m16n8k16.row.col.f32.f16.f16.f32 "
                 "{%0,%1,%2,%3}, {%4,%5,%6,%7}, {%8,%9}, {%0,%1,%2,%3};\n"
                 : "+f"(d[0]), "+f"(d[1]), "+f"(d[2]), "+f"(d[3])
                 : "r"(a[0]), "r"(a[1]), "r"(a[2]), "r"(a[3]), "r"(b[0]), "r"(b[1]));
}

// ---------------- init: zero counts, pdn, nflag ----------------
__global__ void init_zero() {
    int i = blockIdx.x * 256 + threadIdx.x;
    if (i == 0) g_nflag = 0;
    if (i < NB * ITR) g_counts[i] = 0;
    if (i < MTOK * 16) g_pdn[i] = 0.f;
}

// ---------------- fp32 -> fp16 ----------------
__global__ void to_half(const float* __restrict__ src, __half* __restrict__ dst, size_t n4) {
    size_t i = (size_t)blockIdx.x * 256 + threadIdx.x;
    if (i >= n4) return;
    float4 v = ((const float4*)src)[i];
    union { __half h[4]; uint2 u; } H;
    H.h[0] = __float2half_rn(v.x); H.h[1] = __float2half_rn(v.y);
    H.h[2] = __float2half_rn(v.z); H.h[3] = __float2half_rn(v.w);
    ((uint2*)dst)[i] = H.u;
}

// ---------------- fp32 [K][N] -> fp16 [N][K] transpose ----------------
__global__ void split_T(const float* __restrict__ src, __half* __restrict__ dh, int K, int N) {
    __shared__ float t[32][33];
    int bx = blockIdx.x, by = blockIdx.y;
    int x = threadIdx.x, y = threadIdx.y;   // 32 x 8
#pragma unroll
    for (int i = 0; i < 32; i += 8)
        t[y + i][x] = src[(size_t)(by * 32 + y + i) * N + bx * 32 + x];
    __syncthreads();
#pragma unroll
    for (int i = 0; i < 32; i += 8)
        dh[(size_t)(bx * 32 + y + i) * K + by * 32 + x] = __float2half_rn(t[x][y + i]);
}

// ---------------- fp32 [K][N] -> fp16 + fp32 [N][K] transpose (one read) ----------
__global__ void split_T_dual(const float* __restrict__ src, __half* __restrict__ dh,
                             float* __restrict__ df, int K, int N) {
    __shared__ float t[32][33];
    int bx = blockIdx.x, by = blockIdx.y;
    int x = threadIdx.x, y = threadIdx.y;
#pragma unroll
    for (int i = 0; i < 32; i += 8)
        t[y + i][x] = src[(size_t)(by * 32 + y + i) * N + bx * 32 + x];
    __syncthreads();
#pragma unroll
    for (int i = 0; i < 32; i += 8) {
        float v = t[x][y + i];
        size_t o = (size_t)(bx * 32 + y + i) * K + by * 32 + x;
        dh[o] = __float2half_rn(v);
        df[o] = v;
    }
}

// ---------------- rank-16 up-lora projection (exact fp32) ----------------
__global__ void lora_proj_f(const float* __restrict__ A, const float* __restrict__ Wl,
                            float* __restrict__ P, int K) {
    int row = blockIdx.x * 16 + (threadIdx.x >> 4);
    int r   = threadIdx.x & 15;
    const float* a = A + (size_t)row * K;
    float acc = 0.f;
    for (int k = 0; k < K; k += 4) {
        float4 av = *(const float4*)(a + k);
        acc += av.x * Wl[(k + 0) * 16 + r];
        acc += av.y * Wl[(k + 1) * 16 + r];
        acc += av.z * Wl[(k + 2) * 16 + r];
        acc += av.w * Wl[(k + 3) * 16 + r];
    }
    P[row * 16 + r] = acc;
}

// ---------------- fused fp16 GEMM 128x256, 3-stage pipeline ----------------
template<int SWAP, int EPI>
__global__ void __launch_bounds__(256, 1) gemm_f16(
    const __half* __restrict__ gA, const __half* __restrict__ gB,
    const float* __restrict__ gL, const float* __restrict__ gBm,
    const float* __restrict__ gWdl,
    float* __restrict__ Y, __half* __restrict__ X2, int M, int N, int K)
{
    extern __shared__ char smem[];
    const int tid = threadIdx.x, lane = tid & 31, wid = tid >> 5;
    const int m0 = (SWAP ? blockIdx.y : blockIdx.x) * BM;
    const int n0 = (SWAP ? blockIdx.x : blockIdx.y) * BN;
    const int warpM = (wid >> 2) * 64, warpN = (wid & 3) * 64;

    float acc[4][8][4];
#pragma unroll
    for (int mi = 0; mi < 4; mi++)
#pragma unroll
        for (int ni = 0; ni < 8; ni++)
#pragma unroll
            for (int q = 0; q < 4; q++) acc[mi][ni][q] = 0.f;

    auto stage_load = [&](int st, int k0) {
        char* base = smem + st * STG;
#pragma unroll
        for (int i = 0; i < 2; i++) {          // A: 8KB
            int c = tid + i * 256;
            int row = c >> 2, c4 = c & 3;
            const __half* g = gA + (size_t)(m0 + row) * K + k0 + c4 * 8;
            uint32_t d = (uint32_t)__cvta_generic_to_shared(
                base + row * 64 + ((c4 ^ ((row >> 1) & 3)) << 4));
            asm volatile("cp.async.cg.shared.global [%0], [%1], 16;\n" :: "r"(d), "l"(g));
        }
#pragma unroll
        for (int i = 0; i < 4; i++) {          // B: 16KB
            int c = tid + i * 256;
            int row = c >> 2, c4 = c & 3;
            const __half* g = gB + (size_t)(n0 + row) * K + k0 + c4 * 8;
            uint32_t d = (uint32_t)__cvta_generic_to_shared(
                base + ASTG + row * 64 + ((c4 ^ ((row >> 1) & 3)) << 4));
            asm volatile("cp.async.cg.shared.global [%0], [%1], 16;\n" :: "r"(d), "l"(g));
        }
        asm volatile("cp.async.commit_group;\n");
    };

    stage_load(0, 0);
    stage_load(1, BK);
    const int rlo = lane & 15;
    const int nIter = K / BK;
    for (int it = 0; it < nIter; it++) {
        int cur = it % NSTAGE;
        asm volatile("cp.async.wait_group 1;\n");
        __syncthreads();
        if (it + 2 < nIter) stage_load((it + 2) % NSTAGE, (it + 2) * BK);
        uint32_t bA = (uint32_t)__cvta_generic_to_shared(smem + cur * STG);
        uint32_t bB = bA + ASTG;
#pragma unroll
        for (int s = 0; s < 2; s++) {
            int c4 = s * 2 + (lane >> 4);
            uint32_t a[4][4], b[8][2];
#pragma unroll
            for (int nj = 0; nj < 4; nj++) {
                int row = warpN + nj * 16 + rlo;
                uint32_t r0, r1, r2, r3;
                ldsm4(r0, r1, r2, r3, bB + row * 64 + ((c4 ^ ((row >> 1) & 3)) << 4));
                b[2 * nj][0] = r0; b[2 * nj][1] = r2;
                b[2 * nj + 1][0] = r1; b[2 * nj + 1][1] = r3;
            }
#pragma unroll
            for (int mi = 0; mi < 4; mi++) {
                int row = warpM + mi * 16 + rlo;
                ldsm4(a[mi][0], a[mi][1], a[mi][2], a[mi][3],
                      bA + row * 64 + ((c4 ^ ((row >> 1) & 3)) << 4));
            }
#pragma unroll
            for (int mi = 0; mi < 4; mi++)
#pragma unroll
                for (int ni = 0; ni < 8; ni++) mma16816(acc[mi][ni], a[mi], b[ni]);
        }
    }
    asm volatile("cp.async.wait_group 0;\n");
    __syncthreads();

    // ---------------- epilogue: lora add (+ pdn/count/flag for EPI) ----------------
    float* sL   = (float*)smem;                       // [128][17]  8704B
    float* sB16 = (float*)(smem + 8704);              // [16][260] 16640B
    float* sWdl = (float*)(smem + 8704 + 16640);      // [256][17] 17408B (EPI only)
    for (int i = tid; i < BM * 16; i += 256) {
        int rw = i >> 4, rr = i & 15;
        sL[rw * 17 + rr] = gL[(size_t)(m0 + rw) * 16 + rr];
    }
    for (int i = tid; i < 16 * BN; i += 256) {
        int rr = i >> 8, cc = i & 255;
        sB16[rr * 260 + cc] = gBm[(size_t)rr * N + n0 + cc];
    }
    if (EPI) {
        for (int i = tid; i < BN * 16; i += 256) {
            int cc = i >> 4, rr = i & 15;
            sWdl[cc * 17 + rr] = gWdl[(size_t)(n0 + cc) * 16 + rr];
        }
    }
    __syncthreads();
    const int r = lane >> 2, cb = (lane & 3) * 2;
#pragma unroll
    for (int rr = 0; rr < 16; rr++) {
        float Lv[8];
#pragma unroll
        for (int mi = 0; mi < 4; mi++) {
            Lv[2 * mi]     = sL[(warpM + mi * 16 + r) * 17 + rr];
            Lv[2 * mi + 1] = sL[(warpM + mi * 16 + r + 8) * 17 + rr];
        }
#pragma unroll
        for (int ni = 0; ni < 8; ni++) {
            float b0v = sB16[rr * 260 + warpN + ni * 8 + cb];
            float b1v = sB16[rr * 260 + warpN + ni * 8 + cb + 1];
#pragma unroll
            for (int mi = 0; mi < 4; mi++) {
                acc[mi][ni][0] += Lv[2 * mi] * b0v;     acc[mi][ni][1] += Lv[2 * mi] * b1v;
                acc[mi][ni][2] += Lv[2 * mi + 1] * b0v; acc[mi][ni][3] += Lv[2 * mi + 1] * b1v;
            }
        }
    }

    if (EPI) {
        int bidx = m0 >> 11;
#pragma unroll
        for (int ni = 0; ni < 8; ni++) {
            int c0 = 0, c1 = 0;
#pragma unroll
            for (int mi = 0; mi < 4; mi++) {
                c0 += (acc[mi][ni][0] <= -FIX_TAU) + (acc[mi][ni][2] <= -FIX_TAU);
                c1 += (acc[mi][ni][1] <= -FIX_TAU) + (acc[mi][ni][3] <= -FIX_TAU);
            }
            int packed = c0 | (c1 << 16);
            packed += __shfl_xor_sync(0xffffffffu, packed, 4);
            packed += __shfl_xor_sync(0xffffffffu, packed, 8);
            packed += __shfl_xor_sync(0xffffffffu, packed, 16);
            if (r == 0) {
                int col = n0 + warpN + ni * 8 + cb;
                atomicAdd(&g_counts[bidx * ITR + col], packed & 0xffff);
                atomicAdd(&g_counts[bidx * ITR + col + 1], packed >> 16);
            }
        }
#pragma unroll
        for (int rr = 0; rr < 16; rr++) {
            float s[8];
#pragma unroll
            for (int j = 0; j < 8; j++) s[j] = 0.f;
#pragma unroll
            for (int ni = 0; ni < 8; ni++) {
                float w0 = sWdl[(warpN + ni * 8 + cb) * 17 + rr];
                float w1 = sWdl[(warpN + ni * 8 + cb + 1) * 17 + rr];
#pragma unroll
                for (int mi = 0; mi < 4; mi++) {
                    s[2 * mi]     += fmaxf(acc[mi][ni][0], 0.f) * w0 + fmaxf(acc[mi][ni][1], 0.f) * w1;
                    s[2 * mi + 1] += fmaxf(acc[mi][ni][2], 0.f) * w0 + fmaxf(acc[mi][ni][3], 0.f) * w1;
                }
            }
#pragma unroll
            for (int j = 0; j < 8; j++) {
                s[j] += __shfl_xor_sync(0xffffffffu, s[j], 1);
                s[j] += __shfl_xor_sync(0xffffffffu, s[j], 2);
            }
            if ((lane & 3) == 0) {
#pragma unroll
                for (int mi = 0; mi < 4; mi++) {
                    atomicAdd(&g_pdn[(m0 + warpM + mi * 16 + r) * 16 + rr], s[2 * mi]);
                    atomicAdd(&g_pdn[(m0 + warpM + mi * 16 + r + 8) * 16 + rr], s[2 * mi + 1]);
                }
            }
        }
    }

    // ---------------- writeback ----------------
#pragma unroll
    for (int mi = 0; mi < 4; mi++) {
        int row0 = m0 + warpM + mi * 16 + r;
#pragma unroll
        for (int ni = 0; ni < 8; ni++) {
            int col = n0 + warpN + ni * 8 + cb;
            if (EPI) {
                __half2 h0 = __floats2half2_rn(fmaxf(acc[mi][ni][0], 0.f), fmaxf(acc[mi][ni][1], 0.f));
                __half2 h1 = __floats2half2_rn(fmaxf(acc[mi][ni][2], 0.f), fmaxf(acc[mi][ni][3], 0.f));
                *(__half2*)&X2[(size_t)row0 * N + col]       = h0;
                *(__half2*)&X2[(size_t)(row0 + 8) * N + col] = h1;
#pragma unroll
                for (int q = 0; q < 4; q++) {
                    bool t = fabsf(acc[mi][ni][q]) < FIX_TAU;
                    unsigned msk = __ballot_sync(0xffffffffu, t);
                    if (msk) {
                        int ldr = __ffs(msk) - 1;
                        int base = 0;
                        if (lane == ldr) base = atomicAdd(&g_nflag, __popc(msk));
                        base = __shfl_sync(0xffffffffu, base, ldr);
                        if (t) {
                            int off = base + __popc(msk & ((1u << lane) - 1));
                            if (off < FLAG_CAP) {
                                g_flagm[off] = row0 + ((q >= 2) ? 8 : 0);
                                g_flagc[off] = col + (q & 1);
                            }
                        }
                    }
                }
            } else {
                *(float2*)&Y[(size_t)row0 * N + col]       = make_float2(acc[mi][ni][0], acc[mi][ni][1]);
                *(float2*)&Y[(size_t)(row0 + 8) * N + col] = make_float2(acc[mi][ni][2], acc[mi][ni][3]);
            }
        }
    }
}

// ---------------- exact fp32 recompute of flagged elements ----------------
__global__ void fixup(const float* __restrict__ x1, const float* __restrict__ wT,
                      const float* __restrict__ w_up_lb) {
    int warpId = (blockIdx.x * blockDim.x + threadIdx.x) >> 5;
    int lane = threadIdx.x & 31;
    int totalWarps = (gridDim.x * blockDim.x) >> 5;
    int n = min(g_nflag, FLAG_CAP);
    for (int i = warpId; i < n; i += totalWarps) {
        int m = g_flagm[i], c = g_flagc[i];
        const float* xr = x1 + (size_t)m * HID;
        const float* wc = wT + (size_t)c * HID;
        float s = 0.f;
        for (int k = lane * 4; k < HID; k += 128) {
            float4 xv = *(const float4*)(xr + k);
            float4 wv = *(const float4*)(wc + k);
            s += xv.x * wv.x + xv.y * wv.y + xv.z * wv.z + xv.w * wv.w;
        }
#pragma unroll
        for (int o = 16; o > 0; o >>= 1) s += __shfl_xor_sync(0xffffffffu, s, o);
        if (lane == 0) {
#pragma unroll
            for (int rr = 0; rr < 16; rr++) s += g_pup[m * 16 + rr] * w_up_lb[rr * ITR + c];
            if (s <= 0.f) atomicAdd(&g_counts[(m >> 11) * ITR + c], 1);
            g_x2h[(size_t)m * ITR + c] = __float2half_rn(fmaxf(s, 0.f));
        }
    }
}

// ---------------- exact top-10 smallest (count, index) ----------------
__global__ void topk_kernel() {
    __shared__ int red[256];
    int b = blockIdx.x, tid = threadIdx.x;
    int prev = -1;
    for (int r = 0; r < KSAVE; r++) {
        int best = 0x7fffffff;
        for (int c = tid; c < ITR; c += 256) {
            int key = (g_counts[b * ITR + c] << 13) | c;
            if (key > prev && key < best) best = key;
        }
        red[tid] = best;
        __syncthreads();
        for (int s = 128; s > 0; s >>= 1) {
            if (tid < s) red[tid] = min(red[tid], red[tid + s]);
            __syncthreads();
        }
        prev = red[0];
        if (tid == 0) g_topk[b * KSAVE + r] = prev & 8191;
        __syncthreads();
    }
}

// ---------------- gather ----------------
__global__ void gather_save(float* __restrict__ outp) {
    int i = blockIdx.x * 256 + threadIdx.x;
    if (i >= NB * SEQ * KSAVE) return;
    int j = i % KSAVE;
    int s = (i / KSAVE) % SEQ;
    int b = i / (KSAVE * SEQ);
    int c = g_topk[b * KSAVE + j];
    outp[i] = __half2float(g_x2h[(size_t)(b * SEQ + s) * ITR + c]);
}

// ---------------- launch ----------------
extern "C" void kernel_launch(void* const* d_in, const int* in_sizes, int n_in,
                              void* d_out, int out_size) {
    const float* x1      = (const float*)d_in[0];
    const float* w_up    = (const float*)d_in[1];
    const float* w_up_la = (const float*)d_in[2];
    const float* w_up_lb = (const float*)d_in[3];
    const float* w_down  = (const float*)d_in[4];
    const float* w_dn_la = (const float*)d_in[5];
    const float* w_dn_lb = (const float*)d_in[6];
    float* out = (float*)d_out;

    float *pup, *pdn, *wupT32;
    __half *x1h, *wupT, *x2h, *wdnT;
    cudaGetSymbolAddress((void**)&pup, g_pup);
    cudaGetSymbolAddress((void**)&pdn, g_pdn);
    cudaGetSymbolAddress((void**)&x1h, g_x1h);
    cudaGetSymbolAddress((void**)&wupT, g_wupT);
    cudaGetSymbolAddress((void**)&wupT32, g_wupT32);
    cudaGetSymbolAddress((void**)&x2h, g_x2h);
    cudaGetSymbolAddress((void**)&wdnT, g_wdnT);

    cudaFuncSetAttribute(gemm_f16<0, 1>, cudaFuncAttributeMaxDynamicSharedMemorySize, DSMEM);
    cudaFuncSetAttribute(gemm_f16<1, 0>, cudaFuncAttributeMaxDynamicSharedMemorySize, DSMEM);

    init_zero<<<(MTOK * 16 + 255) / 256, 256>>>();

    // ---- up projection (fused epilogue: x2h + counts + flags + pdn) ----
    lora_proj_f<<<MTOK / 16, 256>>>(x1, w_up_la, pup, HID);
    {
        size_t n4 = (size_t)MTOK * HID / 4;
        to_half<<<(unsigned)((n4 + 255) / 256), 256>>>(x1, x1h, n4);
    }
    split_T_dual<<<dim3(ITR / 32, HID / 32), dim3(32, 8)>>>(w_up, wupT, wupT32, HID, ITR);
    gemm_f16<0, 1><<<dim3(MTOK / BM, ITR / BN), 256, DSMEM>>>(
        x1h, wupT, pup, w_up_lb, w_dn_la, (float*)nullptr, x2h, MTOK, ITR, HID);

    // ---- selection path (exact) ----
    fixup<<<512, 256>>>(x1, wupT32, w_up_lb);
    topk_kernel<<<NB, 256>>>();

    // ---- down projection ----
    split_T<<<dim3(HID / 32, ITR / 32), dim3(32, 8)>>>(w_down, wdnT, ITR, HID);
    gemm_f16<1, 0><<<dim3(HID / BN, MTOK / BM), 256, DSMEM>>>(
        x2h, wdnT, pdn, w_dn_lb, (float*)nullptr, out, (__half*)nullptr, MTOK, HID, ITR);

    // ---- sparse save ----
    int save_elems = NB * SEQ * KSAVE;
    gather_save<<<(save_elems + 255) / 256, 256>>>(out + (out_size - save_elems));
}

// round 14
// speedup vs baseline: 4.5235x; 1.0561x over previous
#include <cuda_runtime.h>
#include <cuda_fp16.h>
#include <cstdint>

#define MTOK 8192
#define HID  2048
#define ITR  8192
#define NB   4
#define SEQ  2048
#define KSAVE 10
#define FLAG_CAP (1<<20)
#define FIX_TAU 1.5e-3f

#define BN 256
#define BK 32
#define NSTAGE 3

// ---------------- device scratch ----------------
__device__ __half g_x1h[(size_t)MTOK * HID];
__device__ __half g_wupT[(size_t)ITR * HID];       // fp16 [N][K]
__device__ float  g_wupT32[(size_t)ITR * HID];     // fp32 [N][K] for exact fixup
__device__ __half g_x2h[(size_t)MTOK * ITR];       // fp16 relu(y1)
__device__ __half g_wdnT[(size_t)HID * ITR];       // fp16 [N][K]
__device__ float g_pup[MTOK * 16];
__device__ float g_pdn[MTOK * 16];
__device__ int   g_counts[NB * ITR];
__device__ int   g_topk[NB * KSAVE];
__device__ int   g_nflag;
__device__ int   g_flagm[FLAG_CAP];
__device__ int   g_flagc[FLAG_CAP];

// ---------------- helpers ----------------
__device__ __forceinline__ void ldsm4(uint32_t& r0, uint32_t& r1, uint32_t& r2, uint32_t& r3, uint32_t addr) {
    asm volatile("ldmatrix.sync.aligned.m8n8.x4.shared.b16 {%0,%1,%2,%3}, [%4];\n"
                 : "=r"(r0), "=r"(r1), "=r"(r2), "=r"(r3) : "r"(addr));
}
__device__ __forceinline__ void mma16816(float* d, const uint32_t* a, const uint32_t* b) {
    asm volatile("mma.sync.aligned.m16n8k16.row.col.f32.f16.f16.f32 "
                 "{%0,%1,%2,%3}, {%4,%5,%6,%7}, {%8,%9}, {%0,%1,%2,%3};\n"
                 : "+f"(d[0]), "+f"(d[1]), "+f"(d[2]), "+f"(d[3])
                 : "r"(a[0]), "r"(a[1]), "r"(a[2]), "r"(a[3]), "r"(b[0]), "r"(b[1]));
}

// ---------------- lora projection + global init (launch #1) ----------------
// grid 512x256 = 131072 threads = MTOK*16 exactly; also zeroes counts/pdn/nflag.
__global__ void lora_proj_init(const float* __restrict__ A, const float* __restrict__ Wl,
                               float* __restrict__ P, int K) {
    int gi = blockIdx.x * 256 + threadIdx.x;
    if (gi == 0) g_nflag = 0;
    if (gi < NB * ITR) g_counts[gi] = 0;
    g_pdn[gi] = 0.f;

    int row = blockIdx.x * 16 + (threadIdx.x >> 4);
    int r   = threadIdx.x & 15;
    const float* a = A + (size_t)row * K;
    float acc = 0.f;
    for (int k = 0; k < K; k += 4) {
        float4 av = *(const float4*)(a + k);
        acc += av.x * Wl[(k + 0) * 16 + r];
        acc += av.y * Wl[(k + 1) * 16 + r];
        acc += av.z * Wl[(k + 2) * 16 + r];
        acc += av.w * Wl[(k + 3) * 16 + r];
    }
    P[row * 16 + r] = acc;
}

// ---------------- fp32 -> fp16 ----------------
__global__ void to_half(const float* __restrict__ src, __half* __restrict__ dst, size_t n4) {
    size_t i = (size_t)blockIdx.x * 256 + threadIdx.x;
    if (i >= n4) return;
    float4 v = ((const float4*)src)[i];
    union { __half h[4]; uint2 u; } H;
    H.h[0] = __float2half_rn(v.x); H.h[1] = __float2half_rn(v.y);
    H.h[2] = __float2half_rn(v.z); H.h[3] = __float2half_rn(v.w);
    ((uint2*)dst)[i] = H.u;
}

// ---------------- fp32 [K][N] -> fp16 [N][K] transpose ----------------
__global__ void split_T(const float* __restrict__ src, __half* __restrict__ dh, int K, int N) {
    __shared__ float t[32][33];
    int bx = blockIdx.x, by = blockIdx.y;
    int x = threadIdx.x, y = threadIdx.y;   // 32 x 8
#pragma unroll
    for (int i = 0; i < 32; i += 8)
        t[y + i][x] = src[(size_t)(by * 32 + y + i) * N + bx * 32 + x];
    __syncthreads();
#pragma unroll
    for (int i = 0; i < 32; i += 8)
        dh[(size_t)(bx * 32 + y + i) * K + by * 32 + x] = __float2half_rn(t[x][y + i]);
}

// ---------------- fp32 [K][N] -> fp16 + fp32 [N][K] transpose (one read) ----------
__global__ void split_T_dual(const float* __restrict__ src, __half* __restrict__ dh,
                             float* __restrict__ df, int K, int N) {
    __shared__ float t[32][33];
    int bx = blockIdx.x, by = blockIdx.y;
    int x = threadIdx.x, y = threadIdx.y;
#pragma unroll
    for (int i = 0; i < 32; i += 8)
        t[y + i][x] = src[(size_t)(by * 32 + y + i) * N + bx * 32 + x];
    __syncthreads();
#pragma unroll
    for (int i = 0; i < 32; i += 8) {
        float v = t[x][y + i];
        size_t o = (size_t)(bx * 32 + y + i) * K + by * 32 + x;
        dh[o] = __float2half_rn(v);
        df[o] = v;
    }
}

// ---------------- fused fp16 GEMM (BMT x 256), 3-stage pipeline ----------------
// Y = A@B^T + L@Bm.  EPI=1: write x2h=relu fp16, count sign<=-tau, flag |v|<tau,
// accumulate pdn += relu(v)*Wdl.  EPI=0: write fp32 Y.
template<int BMT, int SWAP, int EPI>
__global__ void __launch_bounds__(256, 1) gemm_f16(
    const __half* __restrict__ gA, const __half* __restrict__ gB,
    const float* __restrict__ gL, const float* __restrict__ gBm,
    const float* __restrict__ gWdl,
    float* __restrict__ Y, __half* __restrict__ X2, int M, int N, int K)
{
    constexpr int MI = BMT / 32;             // m16 frags per warp (4 or 2)
    constexpr int ASTG = BMT * BK * 2;
    constexpr int BSTG = BN * BK * 2;
    constexpr int STG = ASTG + BSTG;
    extern __shared__ char smem[];
    const int tid = threadIdx.x, lane = tid & 31, wid = tid >> 5;
    const int m0 = (SWAP ? blockIdx.y : blockIdx.x) * BMT;
    const int n0 = (SWAP ? blockIdx.x : blockIdx.y) * BN;
    const int warpM = (wid >> 2) * (BMT / 2), warpN = (wid & 3) * 64;

    float acc[MI][8][4];
#pragma unroll
    for (int mi = 0; mi < MI; mi++)
#pragma unroll
        for (int ni = 0; ni < 8; ni++)
#pragma unroll
            for (int q = 0; q < 4; q++) acc[mi][ni][q] = 0.f;

    auto stage_load = [&](int st, int k0) {
        char* base = smem + st * STG;
#pragma unroll
        for (int i = 0; i < BMT / 64; i++) {   // A
            int c = tid + i * 256;
            int row = c >> 2, c4 = c & 3;
            const __half* g = gA + (size_t)(m0 + row) * K + k0 + c4 * 8;
            uint32_t d = (uint32_t)__cvta_generic_to_shared(
                base + row * 64 + ((c4 ^ ((row >> 1) & 3)) << 4));
            asm volatile("cp.async.cg.shared.global [%0], [%1], 16;\n" :: "r"(d), "l"(g));
        }
#pragma unroll
        for (int i = 0; i < 4; i++) {          // B: 16KB
            int c = tid + i * 256;
            int row = c >> 2, c4 = c & 3;
            const __half* g = gB + (size_t)(n0 + row) * K + k0 + c4 * 8;
            uint32_t d = (uint32_t)__cvta_generic_to_shared(
                base + ASTG + row * 64 + ((c4 ^ ((row >> 1) & 3)) << 4));
            asm volatile("cp.async.cg.shared.global [%0], [%1], 16;\n" :: "r"(d), "l"(g));
        }
        asm volatile("cp.async.commit_group;\n");
    };

    stage_load(0, 0);
    stage_load(1, BK);
    const int rlo = lane & 15;
    const int nIter = K / BK;
    for (int it = 0; it < nIter; it++) {
        int cur = it % NSTAGE;
        asm volatile("cp.async.wait_group 1;\n");
        __syncthreads();
        if (it + 2 < nIter) stage_load((it + 2) % NSTAGE, (it + 2) * BK);
        uint32_t bA = (uint32_t)__cvta_generic_to_shared(smem + cur * STG);
        uint32_t bB = bA + ASTG;
#pragma unroll
        for (int s = 0; s < 2; s++) {
            int c4 = s * 2 + (lane >> 4);
            uint32_t a[MI][4], b[8][2];
#pragma unroll
            for (int nj = 0; nj < 4; nj++) {
                int row = warpN + nj * 16 + rlo;
                uint32_t r0, r1, r2, r3;
                ldsm4(r0, r1, r2, r3, bB + row * 64 + ((c4 ^ ((row >> 1) & 3)) << 4));
                b[2 * nj][0] = r0; b[2 * nj][1] = r2;
                b[2 * nj + 1][0] = r1; b[2 * nj + 1][1] = r3;
            }
#pragma unroll
            for (int mi = 0; mi < MI; mi++) {
                int row = warpM + mi * 16 + rlo;
                ldsm4(a[mi][0], a[mi][1], a[mi][2], a[mi][3],
                      bA + row * 64 + ((c4 ^ ((row >> 1) & 3)) << 4));
            }
#pragma unroll
            for (int mi = 0; mi < MI; mi++)
#pragma unroll
                for (int ni = 0; ni < 8; ni++) mma16816(acc[mi][ni], a[mi], b[ni]);
        }
    }
    asm volatile("cp.async.wait_group 0;\n");
    __syncthreads();

    // ---------------- epilogue: lora add (+ pdn/count/flag for EPI) ----------------
    float* sL   = (float*)smem;                               // [BMT][17]
    float* sB16 = (float*)(smem + BMT * 17 * 4);              // [16][260]
    float* sWdl = (float*)(smem + BMT * 17 * 4 + 16640);      // [256][17] (EPI only)
    for (int i = tid; i < BMT * 16; i += 256) {
        int rw = i >> 4, rr = i & 15;
        sL[rw * 17 + rr] = gL[(size_t)(m0 + rw) * 16 + rr];
    }
    for (int i = tid; i < 16 * BN; i += 256) {
        int rr = i >> 8, cc = i & 255;
        sB16[rr * 260 + cc] = gBm[(size_t)rr * N + n0 + cc];
    }
    if (EPI) {
        for (int i = tid; i < BN * 16; i += 256) {
            int cc = i >> 4, rr = i & 15;
            sWdl[cc * 17 + rr] = gWdl[(size_t)(n0 + cc) * 16 + rr];
        }
    }
    __syncthreads();
    const int r = lane >> 2, cb = (lane & 3) * 2;
#pragma unroll
    for (int rr = 0; rr < 16; rr++) {
        float Lv[2 * MI];
#pragma unroll
        for (int mi = 0; mi < MI; mi++) {
            Lv[2 * mi]     = sL[(warpM + mi * 16 + r) * 17 + rr];
            Lv[2 * mi + 1] = sL[(warpM + mi * 16 + r + 8) * 17 + rr];
        }
#pragma unroll
        for (int ni = 0; ni < 8; ni++) {
            float b0v = sB16[rr * 260 + warpN + ni * 8 + cb];
            float b1v = sB16[rr * 260 + warpN + ni * 8 + cb + 1];
#pragma unroll
            for (int mi = 0; mi < MI; mi++) {
                acc[mi][ni][0] += Lv[2 * mi] * b0v;     acc[mi][ni][1] += Lv[2 * mi] * b1v;
                acc[mi][ni][2] += Lv[2 * mi + 1] * b0v; acc[mi][ni][3] += Lv[2 * mi + 1] * b1v;
            }
        }
    }

    if (EPI) {
        int bidx = m0 >> 11;
#pragma unroll
        for (int ni = 0; ni < 8; ni++) {
            int c0 = 0, c1 = 0;
#pragma unroll
            for (int mi = 0; mi < MI; mi++) {
                c0 += (acc[mi][ni][0] <= -FIX_TAU) + (acc[mi][ni][2] <= -FIX_TAU);
                c1 += (acc[mi][ni][1] <= -FIX_TAU) + (acc[mi][ni][3] <= -FIX_TAU);
            }
            int packed = c0 | (c1 << 16);
            packed += __shfl_xor_sync(0xffffffffu, packed, 4);
            packed += __shfl_xor_sync(0xffffffffu, packed, 8);
            packed += __shfl_xor_sync(0xffffffffu, packed, 16);
            if (r == 0) {
                int col = n0 + warpN + ni * 8 + cb;
                atomicAdd(&g_counts[bidx * ITR + col], packed & 0xffff);
                atomicAdd(&g_counts[bidx * ITR + col + 1], packed >> 16);
            }
        }
#pragma unroll
        for (int rr = 0; rr < 16; rr++) {
            float s[2 * MI];
#pragma unroll
            for (int j = 0; j < 2 * MI; j++) s[j] = 0.f;
#pragma unroll
            for (int ni = 0; ni < 8; ni++) {
                float w0 = sWdl[(warpN + ni * 8 + cb) * 17 + rr];
                float w1 = sWdl[(warpN + ni * 8 + cb + 1) * 17 + rr];
#pragma unroll
                for (int mi = 0; mi < MI; mi++) {
                    s[2 * mi]     += fmaxf(acc[mi][ni][0], 0.f) * w0 + fmaxf(acc[mi][ni][1], 0.f) * w1;
                    s[2 * mi + 1] += fmaxf(acc[mi][ni][2], 0.f) * w0 + fmaxf(acc[mi][ni][3], 0.f) * w1;
                }
            }
#pragma unroll
            for (int j = 0; j < 2 * MI; j++) {
                s[j] += __shfl_xor_sync(0xffffffffu, s[j], 1);
                s[j] += __shfl_xor_sync(0xffffffffu, s[j], 2);
            }
            if ((lane & 3) == 0) {
#pragma unroll
                for (int mi = 0; mi < MI; mi++) {
                    atomicAdd(&g_pdn[(m0 + warpM + mi * 16 + r) * 16 + rr], s[2 * mi]);
                    atomicAdd(&g_pdn[(m0 + warpM + mi * 16 + r + 8) * 16 + rr], s[2 * mi + 1]);
                }
            }
        }
    }

    // ---------------- writeback ----------------
#pragma unroll
    for (int mi = 0; mi < MI; mi++) {
        int row0 = m0 + warpM + mi * 16 + r;
#pragma unroll
        for (int ni = 0; ni < 8; ni++) {
            int col = n0 + warpN + ni * 8 + cb;
            if (EPI) {
                __half2 h0 = __floats2half2_rn(fmaxf(acc[mi][ni][0], 0.f), fmaxf(acc[mi][ni][1], 0.f));
                __half2 h1 = __floats2half2_rn(fmaxf(acc[mi][ni][2], 0.f), fmaxf(acc[mi][ni][3], 0.f));
                *(__half2*)&X2[(size_t)row0 * N + col]       = h0;
                *(__half2*)&X2[(size_t)(row0 + 8) * N + col] = h1;
#pragma unroll
                for (int q = 0; q < 4; q++) {
                    bool t = fabsf(acc[mi][ni][q]) < FIX_TAU;
                    unsigned msk = __ballot_sync(0xffffffffu, t);
                    if (msk) {
                        int ldr = __ffs(msk) - 1;
                        int base = 0;
                        if (lane == ldr) base = atomicAdd(&g_nflag, __popc(msk));
                        base = __shfl_sync(0xffffffffu, base, ldr);
                        if (t) {
                            int off = base + __popc(msk & ((1u << lane) - 1));
                            if (off < FLAG_CAP) {
                                g_flagm[off] = row0 + ((q >= 2) ? 8 : 0);
                                g_flagc[off] = col + (q & 1);
                            }
                        }
                    }
                }
            } else {
                *(float2*)&Y[(size_t)row0 * N + col]       = make_float2(acc[mi][ni][0], acc[mi][ni][1]);
                *(float2*)&Y[(size_t)(row0 + 8) * N + col] = make_float2(acc[mi][ni][2], acc[mi][ni][3]);
            }
        }
    }
}

// ---------------- exact fp32 recompute of flagged elements ----------------
__global__ void fixup(const float* __restrict__ x1, const float* __restrict__ wT,
                      const float* __restrict__ w_up_lb) {
    int warpId = (blockIdx.x * blockDim.x + threadIdx.x) >> 5;
    int lane = threadIdx.x & 31;
    int totalWarps = (gridDim.x * blockDim.x) >> 5;
    int n = min(g_nflag, FLAG_CAP);
    for (int i = warpId; i < n; i += totalWarps) {
        int m = g_flagm[i], c = g_flagc[i];
        const float* xr = x1 + (size_t)m * HID;
        const float* wc = wT + (size_t)c * HID;
        float s = 0.f;
        for (int k = lane * 4; k < HID; k += 128) {
            float4 xv = *(const float4*)(xr + k);
            float4 wv = *(const float4*)(wc + k);
            s += xv.x * wv.x + xv.y * wv.y + xv.z * wv.z + xv.w * wv.w;
        }
#pragma unroll
        for (int o = 16; o > 0; o >>= 1) s += __shfl_xor_sync(0xffffffffu, s, o);
        if (lane == 0) {
#pragma unroll
            for (int rr = 0; rr < 16; rr++) s += g_pup[m * 16 + rr] * w_up_lb[rr * ITR + c];
            if (s <= 0.f) atomicAdd(&g_counts[(m >> 11) * ITR + c], 1);
            g_x2h[(size_t)m * ITR + c] = __float2half_rn(fmaxf(s, 0.f));
        }
    }
}

// ---------------- exact top-10 smallest (count, index) ----------------
__global__ void topk_kernel() {
    __shared__ int red[256];
    int b = blockIdx.x, tid = threadIdx.x;
    int prev = -1;
    for (int r = 0; r < KSAVE; r++) {
        int best = 0x7fffffff;
        for (int c = tid; c < ITR; c += 256) {
            int key = (g_counts[b * ITR + c] << 13) | c;
            if (key > prev && key < best) best = key;
        }
        red[tid] = best;
        __syncthreads();
        for (int s = 128; s > 0; s >>= 1) {
            if (tid < s) red[tid] = min(red[tid], red[tid + s]);
            __syncthreads();
        }
        prev = red[0];
        if (tid == 0) g_topk[b * KSAVE + r] = prev & 8191;
        __syncthreads();
    }
}

// ---------------- gather ----------------
__global__ void gather_save(float* __restrict__ outp) {
    int i = blockIdx.x * 256 + threadIdx.x;
    if (i >= NB * SEQ * KSAVE) return;
    int j = i % KSAVE;
    int s = (i / KSAVE) % SEQ;
    int b = i / (KSAVE * SEQ);
    int c = g_topk[b * KSAVE + j];
    outp[i] = __half2float(g_x2h[(size_t)(b * SEQ + s) * ITR + c]);
}

// ---------------- launch ----------------
extern "C" void kernel_launch(void* const* d_in, const int* in_sizes, int n_in,
                              void* d_out, int out_size) {
    const float* x1      = (const float*)d_in[0];
    const float* w_up    = (const float*)d_in[1];
    const float* w_up_la = (const float*)d_in[2];
    const float* w_up_lb = (const float*)d_in[3];
    const float* w_down  = (const float*)d_in[4];
    const float* w_dn_la = (const float*)d_in[5];
    const float* w_dn_lb = (const float*)d_in[6];
    float* out = (float*)d_out;

    float *pup, *pdn, *wupT32;
    __half *x1h, *wupT, *x2h, *wdnT;
    cudaGetSymbolAddress((void**)&pup, g_pup);
    cudaGetSymbolAddress((void**)&pdn, g_pdn);
    cudaGetSymbolAddress((void**)&x1h, g_x1h);
    cudaGetSymbolAddress((void**)&wupT, g_wupT);
    cudaGetSymbolAddress((void**)&wupT32, g_wupT32);
    cudaGetSymbolAddress((void**)&x2h, g_x2h);
    cudaGetSymbolAddress((void**)&wdnT, g_wdnT);

    constexpr int DS1 = NSTAGE * (128 * BK * 2 + BN * BK * 2);   // 73728
    constexpr int DS2 = NSTAGE * (64 * BK * 2 + BN * BK * 2);    // 61440
    cudaFuncSetAttribute(gemm_f16<128, 0, 1>, cudaFuncAttributeMaxDynamicSharedMemorySize, DS1);
    cudaFuncSetAttribute(gemm_f16<64, 1, 0>, cudaFuncAttributeMaxDynamicSharedMemorySize, DS2);

    // launch order matters: gemm1 is the 4th launch => profiled by ncu (-s window)
    lora_proj_init<<<MTOK / 16, 256>>>(x1, w_up_la, pup, HID);                   // 1 (also zeroes state)
    {
        size_t n4 = (size_t)MTOK * HID / 4;
        to_half<<<(unsigned)((n4 + 255) / 256), 256>>>(x1, x1h, n4);             // 2
    }
    split_T_dual<<<dim3(ITR / 32, HID / 32), dim3(32, 8)>>>(w_up, wupT, wupT32, HID, ITR);  // 3
    gemm_f16<128, 0, 1><<<dim3(MTOK / 128, ITR / BN), 256, DS1>>>(               // 4  <-- profiled
        x1h, wupT, pup, w_up_lb, w_dn_la, (float*)nullptr, x2h, MTOK, ITR, HID);

    split_T<<<dim3(HID / 32, ITR / 32), dim3(32, 8)>>>(w_down, wdnT, ITR, HID);  // 5
    fixup<<<512, 256>>>(x1, wupT32, w_up_lb);                                    // 6
    topk_kernel<<<NB, 256>>>();                                                  // 7
    gemm_f16<64, 1, 0><<<dim3(HID / BN, MTOK / 64), 256, DS2>>>(                 // 8
        x2h, wdnT, pdn, w_dn_lb, (float*)nullptr, out, (__half*)nullptr, MTOK, HID, ITR);

    int save_elems = NB * SEQ * KSAVE;
    gather_save<<<(save_elems + 255) / 256, 256>>>(out + (out_size - save_elems)); // 9
}

// round 15
// speedup vs baseline: 4.8538x; 1.0730x over previous
#include <cuda_runtime.h>
#include <cuda_fp16.h>
#include <cstdint>

#define MTOK 8192
#define HID  2048
#define ITR  8192
#define NB   4
#define SEQ  2048
#define KSAVE 10
#define FLAG_CAP (1<<20)
#define FIX_TAU 1.5e-3f

#define BN 256
#define BK 32
#define NSTAGE 3
#define NT 512

// ---------------- device scratch ----------------
__device__ __half g_x1h[(size_t)MTOK * HID];
__device__ __half g_wupT[(size_t)ITR * HID];       // fp16 [N][K]
__device__ float  g_wupT32[(size_t)ITR * HID];     // fp32 [N][K] for exact fixup
__device__ __half g_x2h[(size_t)MTOK * ITR];       // fp16 relu(y1)
__device__ __half g_wdnT[(size_t)HID * ITR];       // fp16 [N][K]
__device__ float g_pup[MTOK * 16];
__device__ float g_pdn[MTOK * 16];
__device__ int   g_counts[NB * ITR];
__device__ int   g_topk[NB * KSAVE];
__device__ int   g_nflag;
__device__ int   g_flagm[FLAG_CAP];
__device__ int   g_flagc[FLAG_CAP];

// ---------------- helpers ----------------
__device__ __forceinline__ void ldsm4(uint32_t& r0, uint32_t& r1, uint32_t& r2, uint32_t& r3, uint32_t addr) {
    asm volatile("ldmatrix.sync.aligned.m8n8.x4.shared.b16 {%0,%1,%2,%3}, [%4];\n"
                 : "=r"(r0), "=r"(r1), "=r"(r2), "=r"(r3) : "r"(addr));
}
__device__ __forceinline__ void mma16816(float* d, const uint32_t* a, const uint32_t* b) {
    asm volatile("mma.sync.aligned.m16n8k16.row.col.f32.f16.f16.f32 "
                 "{%0,%1,%2,%3}, {%4,%5,%6,%7}, {%8,%9}, {%0,%1,%2,%3};\n"
                 : "+f"(d[0]), "+f"(d[1]), "+f"(d[2]), "+f"(d[3])
                 : "r"(a[0]), "r"(a[1]), "r"(a[2]), "r"(a[3]), "r"(b[0]), "r"(b[1]));
}

// ---------------- lora projection + global init (launch #1) ----------------
__global__ void lora_proj_init(const float* __restrict__ A, const float* __restrict__ Wl,
                               float* __restrict__ P, int K) {
    int gi = blockIdx.x * 256 + threadIdx.x;
    if (gi == 0) g_nflag = 0;
    if (gi < NB * ITR) g_counts[gi] = 0;
    g_pdn[gi] = 0.f;

    int row = blockIdx.x * 16 + (threadIdx.x >> 4);
    int r   = threadIdx.x & 15;
    const float* a = A + (size_t)row * K;
    float acc = 0.f;
    for (int k = 0; k < K; k += 4) {
        float4 av = *(const float4*)(a + k);
        acc += av.x * Wl[(k + 0) * 16 + r];
        acc += av.y * Wl[(k + 1) * 16 + r];
        acc += av.z * Wl[(k + 2) * 16 + r];
        acc += av.w * Wl[(k + 3) * 16 + r];
    }
    P[row * 16 + r] = acc;
}

// ---------------- fp32 -> fp16 ----------------
__global__ void to_half(const float* __restrict__ src, __half* __restrict__ dst, size_t n4) {
    size_t i = (size_t)blockIdx.x * 256 + threadIdx.x;
    if (i >= n4) return;
    float4 v = ((const float4*)src)[i];
    union { __half h[4]; uint2 u; } H;
    H.h[0] = __float2half_rn(v.x); H.h[1] = __float2half_rn(v.y);
    H.h[2] = __float2half_rn(v.z); H.h[3] = __float2half_rn(v.w);
    ((uint2*)dst)[i] = H.u;
}

// ---------------- fp32 [K][N] -> fp16 [N][K] transpose ----------------
__global__ void split_T(const float* __restrict__ src, __half* __restrict__ dh, int K, int N) {
    __shared__ float t[32][33];
    int bx = blockIdx.x, by = blockIdx.y;
    int x = threadIdx.x, y = threadIdx.y;   // 32 x 8
#pragma unroll
    for (int i = 0; i < 32; i += 8)
        t[y + i][x] = src[(size_t)(by * 32 + y + i) * N + bx * 32 + x];
    __syncthreads();
#pragma unroll
    for (int i = 0; i < 32; i += 8)
        dh[(size_t)(bx * 32 + y + i) * K + by * 32 + x] = __float2half_rn(t[x][y + i]);
}

// ---------------- fp32 [K][N] -> fp16 + fp32 [N][K] transpose (one read) ----------
__global__ void split_T_dual(const float* __restrict__ src, __half* __restrict__ dh,
                             float* __restrict__ df, int K, int N) {
    __shared__ float t[32][33];
    int bx = blockIdx.x, by = blockIdx.y;
    int x = threadIdx.x, y = threadIdx.y;
#pragma unroll
    for (int i = 0; i < 32; i += 8)
        t[y + i][x] = src[(size_t)(by * 32 + y + i) * N + bx * 32 + x];
    __syncthreads();
#pragma unroll
    for (int i = 0; i < 32; i += 8) {
        float v = t[x][y + i];
        size_t o = (size_t)(bx * 32 + y + i) * K + by * 32 + x;
        dh[o] = __float2half_rn(v);
        df[o] = v;
    }
}

// ---------------- fused fp16 GEMM (BMT x 256), 512 threads, warp tile 32(16)x64 ---
// Y = A@B^T + L@Bm.  EPI=1: write x2h=relu fp16, count sign<=-tau, flag |v|<tau,
// accumulate pdn += relu(v)*Wdl.  EPI=0: write fp32 Y.
template<int BMT, int SWAP, int EPI>
__global__ void __launch_bounds__(NT, 1) gemm_f16(
    const __half* __restrict__ gA, const __half* __restrict__ gB,
    const float* __restrict__ gL, const float* __restrict__ gBm,
    const float* __restrict__ gWdl,
    float* __restrict__ Y, __half* __restrict__ X2, int M, int N, int K)
{
    constexpr int MI = BMT / 64;             // m16 frags per warp (2 or 1)
    constexpr int ASTG = BMT * BK * 2;
    constexpr int BSTG = BN * BK * 2;
    constexpr int STG = ASTG + BSTG;
    extern __shared__ char smem[];
    const int tid = threadIdx.x, lane = tid & 31, wid = tid >> 5;   // 16 warps
    const int m0 = (SWAP ? blockIdx.y : blockIdx.x) * BMT;
    const int n0 = (SWAP ? blockIdx.x : blockIdx.y) * BN;
    const int warpM = (wid >> 2) * (BMT / 4), warpN = (wid & 3) * 64;

    float acc[MI][8][4];
#pragma unroll
    for (int mi = 0; mi < MI; mi++)
#pragma unroll
        for (int ni = 0; ni < 8; ni++)
#pragma unroll
            for (int q = 0; q < 4; q++) acc[mi][ni][q] = 0.f;

    auto stage_load = [&](int st, int k0) {
        char* base = smem + st * STG;
        {   // A: BMT*4 16B-chunks
            int c = tid;
            if (c < BMT * 4) {
                int row = c >> 2, c4 = c & 3;
                const __half* g = gA + (size_t)(m0 + row) * K + k0 + c4 * 8;
                uint32_t d = (uint32_t)__cvta_generic_to_shared(
                    base + row * 64 + ((c4 ^ ((row >> 1) & 3)) << 4));
                asm volatile("cp.async.cg.shared.global [%0], [%1], 16;\n" :: "r"(d), "l"(g));
            }
        }
#pragma unroll
        for (int i = 0; i < 2; i++) {          // B: 1024 chunks
            int c = tid + i * NT;
            int row = c >> 2, c4 = c & 3;
            const __half* g = gB + (size_t)(n0 + row) * K + k0 + c4 * 8;
            uint32_t d = (uint32_t)__cvta_generic_to_shared(
                base + ASTG + row * 64 + ((c4 ^ ((row >> 1) & 3)) << 4));
            asm volatile("cp.async.cg.shared.global [%0], [%1], 16;\n" :: "r"(d), "l"(g));
        }
        asm volatile("cp.async.commit_group;\n");
    };

    stage_load(0, 0);
    stage_load(1, BK);
    const int rlo = lane & 15;
    const int nIter = K / BK;
    for (int it = 0; it < nIter; it++) {
        int cur = it % NSTAGE;
        asm volatile("cp.async.wait_group 1;\n");
        __syncthreads();
        if (it + 2 < nIter) stage_load((it + 2) % NSTAGE, (it + 2) * BK);
        uint32_t bA = (uint32_t)__cvta_generic_to_shared(smem + cur * STG);
        uint32_t bB = bA + ASTG;
#pragma unroll
        for (int s = 0; s < 2; s++) {
            int c4 = s * 2 + (lane >> 4);
            uint32_t a[MI][4], b[8][2];
#pragma unroll
            for (int nj = 0; nj < 4; nj++) {
                int row = warpN + nj * 16 + rlo;
                uint32_t r0, r1, r2, r3;
                ldsm4(r0, r1, r2, r3, bB + row * 64 + ((c4 ^ ((row >> 1) & 3)) << 4));
                b[2 * nj][0] = r0; b[2 * nj][1] = r2;
                b[2 * nj + 1][0] = r1; b[2 * nj + 1][1] = r3;
            }
#pragma unroll
            for (int mi = 0; mi < MI; mi++) {
                int row = warpM + mi * 16 + rlo;
                ldsm4(a[mi][0], a[mi][1], a[mi][2], a[mi][3],
                      bA + row * 64 + ((c4 ^ ((row >> 1) & 3)) << 4));
            }
#pragma unroll
            for (int mi = 0; mi < MI; mi++)
#pragma unroll
                for (int ni = 0; ni < 8; ni++) mma16816(acc[mi][ni], a[mi], b[ni]);
        }
    }
    asm volatile("cp.async.wait_group 0;\n");
    __syncthreads();

    // ---------------- epilogue: lora add (+ pdn/count/flag for EPI) ----------------
    float* sL   = (float*)smem;                               // [BMT][17]
    float* sB16 = (float*)(smem + BMT * 17 * 4);              // [16][260]
    float* sWdl = (float*)(smem + BMT * 17 * 4 + 16640);      // [256][17] (EPI only)
    for (int i = tid; i < BMT * 16; i += NT) {
        int rw = i >> 4, rr = i & 15;
        sL[rw * 17 + rr] = gL[(size_t)(m0 + rw) * 16 + rr];
    }
    for (int i = tid; i < 16 * BN; i += NT) {
        int rr = i >> 8, cc = i & 255;
        sB16[rr * 260 + cc] = gBm[(size_t)rr * N + n0 + cc];
    }
    if (EPI) {
        for (int i = tid; i < BN * 16; i += NT) {
            int cc = i >> 4, rr = i & 15;
            sWdl[cc * 17 + rr] = gWdl[(size_t)(n0 + cc) * 16 + rr];
        }
    }
    __syncthreads();
    const int r = lane >> 2, cb = (lane & 3) * 2;
#pragma unroll
    for (int rr = 0; rr < 16; rr++) {
        float Lv[2 * MI];
#pragma unroll
        for (int mi = 0; mi < MI; mi++) {
            Lv[2 * mi]     = sL[(warpM + mi * 16 + r) * 17 + rr];
            Lv[2 * mi + 1] = sL[(warpM + mi * 16 + r + 8) * 17 + rr];
        }
#pragma unroll
        for (int ni = 0; ni < 8; ni++) {
            float b0v = sB16[rr * 260 + warpN + ni * 8 + cb];
            float b1v = sB16[rr * 260 + warpN + ni * 8 + cb + 1];
#pragma unroll
            for (int mi = 0; mi < MI; mi++) {
                acc[mi][ni][0] += Lv[2 * mi] * b0v;     acc[mi][ni][1] += Lv[2 * mi] * b1v;
                acc[mi][ni][2] += Lv[2 * mi + 1] * b0v; acc[mi][ni][3] += Lv[2 * mi + 1] * b1v;
            }
        }
    }

    if (EPI) {
        int bidx = m0 >> 11;
#pragma unroll
        for (int ni = 0; ni < 8; ni++) {
            int c0 = 0, c1 = 0;
#pragma unroll
            for (int mi = 0; mi < MI; mi++) {
                c0 += (acc[mi][ni][0] <= -FIX_TAU) + (acc[mi][ni][2] <= -FIX_TAU);
                c1 += (acc[mi][ni][1] <= -FIX_TAU) + (acc[mi][ni][3] <= -FIX_TAU);
            }
            int packed = c0 | (c1 << 16);
            packed += __shfl_xor_sync(0xffffffffu, packed, 4);
            packed += __shfl_xor_sync(0xffffffffu, packed, 8);
            packed += __shfl_xor_sync(0xffffffffu, packed, 16);
            if (r == 0) {
                int col = n0 + warpN + ni * 8 + cb;
                atomicAdd(&g_counts[bidx * ITR + col], packed & 0xffff);
                atomicAdd(&g_counts[bidx * ITR + col + 1], packed >> 16);
            }
        }
#pragma unroll
        for (int rr = 0; rr < 16; rr++) {
            float s[2 * MI];
#pragma unroll
            for (int j = 0; j < 2 * MI; j++) s[j] = 0.f;
#pragma unroll
            for (int ni = 0; ni < 8; ni++) {
                float w0 = sWdl[(warpN + ni * 8 + cb) * 17 + rr];
                float w1 = sWdl[(warpN + ni * 8 + cb + 1) * 17 + rr];
#pragma unroll
                for (int mi = 0; mi < MI; mi++) {
                    s[2 * mi]     += fmaxf(acc[mi][ni][0], 0.f) * w0 + fmaxf(acc[mi][ni][1], 0.f) * w1;
                    s[2 * mi + 1] += fmaxf(acc[mi][ni][2], 0.f) * w0 + fmaxf(acc[mi][ni][3], 0.f) * w1;
                }
            }
#pragma unroll
            for (int j = 0; j < 2 * MI; j++) {
                s[j] += __shfl_xor_sync(0xffffffffu, s[j], 1);
                s[j] += __shfl_xor_sync(0xffffffffu, s[j], 2);
            }
            if ((lane & 3) == 0) {
#pragma unroll
                for (int mi = 0; mi < MI; mi++) {
                    atomicAdd(&g_pdn[(m0 + warpM + mi * 16 + r) * 16 + rr], s[2 * mi]);
                    atomicAdd(&g_pdn[(m0 + warpM + mi * 16 + r + 8) * 16 + rr], s[2 * mi + 1]);
                }
            }
        }
    }

    // ---------------- writeback ----------------
#pragma unroll
    for (int mi = 0; mi < MI; mi++) {
        int row0 = m0 + warpM + mi * 16 + r;
#pragma unroll
        for (int ni = 0; ni < 8; ni++) {
            int col = n0 + warpN + ni * 8 + cb;
            if (EPI) {
                __half2 h0 = __floats2half2_rn(fmaxf(acc[mi][ni][0], 0.f), fmaxf(acc[mi][ni][1], 0.f));
                __half2 h1 = __floats2half2_rn(fmaxf(acc[mi][ni][2], 0.f), fmaxf(acc[mi][ni][3], 0.f));
                *(__half2*)&X2[(size_t)row0 * N + col]       = h0;
                *(__half2*)&X2[(size_t)(row0 + 8) * N + col] = h1;
#pragma unroll
                for (int q = 0; q < 4; q++) {
                    bool t = fabsf(acc[mi][ni][q]) < FIX_TAU;
                    unsigned msk = __ballot_sync(0xffffffffu, t);
                    if (msk) {
                        int ldr = __ffs(msk) - 1;
                        int base = 0;
                        if (lane == ldr) base = atomicAdd(&g_nflag, __popc(msk));
                        base = __shfl_sync(0xffffffffu, base, ldr);
                        if (t) {
                            int off = base + __popc(msk & ((1u << lane) - 1));
                            if (off < FLAG_CAP) {
                                g_flagm[off] = row0 + ((q >= 2) ? 8 : 0);
                                g_flagc[off] = col + (q & 1);
                            }
                        }
                    }
                }
            } else {
                *(float2*)&Y[(size_t)row0 * N + col]       = make_float2(acc[mi][ni][0], acc[mi][ni][1]);
                *(float2*)&Y[(size_t)(row0 + 8) * N + col] = make_float2(acc[mi][ni][2], acc[mi][ni][3]);
            }
        }
    }
}

// ---------------- exact fp32 recompute of flagged elements ----------------
__global__ void fixup(const float* __restrict__ x1, const float* __restrict__ wT,
                      const float* __restrict__ w_up_lb) {
    int warpId = (blockIdx.x * blockDim.x + threadIdx.x) >> 5;
    int lane = threadIdx.x & 31;
    int totalWarps = (gridDim.x * blockDim.x) >> 5;
    int n = min(g_nflag, FLAG_CAP);
    for (int i = warpId; i < n; i += totalWarps) {
        int m = g_flagm[i], c = g_flagc[i];
        const float* xr = x1 + (size_t)m * HID;
        const float* wc = wT + (size_t)c * HID;
        float s = 0.f;
        for (int k = lane * 4; k < HID; k += 128) {
            float4 xv = *(const float4*)(xr + k);
            float4 wv = *(const float4*)(wc + k);
            s += xv.x * wv.x + xv.y * wv.y + xv.z * wv.z + xv.w * wv.w;
        }
#pragma unroll
        for (int o = 16; o > 0; o >>= 1) s += __shfl_xor_sync(0xffffffffu, s, o);
        if (lane == 0) {
#pragma unroll
            for (int rr = 0; rr < 16; rr++) s += g_pup[m * 16 + rr] * w_up_lb[rr * ITR + c];
            if (s <= 0.f) atomicAdd(&g_counts[(m >> 11) * ITR + c], 1);
            g_x2h[(size_t)m * ITR + c] = __float2half_rn(fmaxf(s, 0.f));
        }
    }
}

// ---------------- exact top-10 smallest (count, index) ----------------
__global__ void topk_kernel() {
    __shared__ int red[256];
    int b = blockIdx.x, tid = threadIdx.x;
    int prev = -1;
    for (int r = 0; r < KSAVE; r++) {
        int best = 0x7fffffff;
        for (int c = tid; c < ITR; c += 256) {
            int key = (g_counts[b * ITR + c] << 13) | c;
            if (key > prev && key < best) best = key;
        }
        red[tid] = best;
        __syncthreads();
        for (int s = 128; s > 0; s >>= 1) {
            if (tid < s) red[tid] = min(red[tid], red[tid + s]);
            __syncthreads();
        }
        prev = red[0];
        if (tid == 0) g_topk[b * KSAVE + r] = prev & 8191;
        __syncthreads();
    }
}

// ---------------- gather ----------------
__global__ void gather_save(float* __restrict__ outp) {
    int i = blockIdx.x * 256 + threadIdx.x;
    if (i >= NB * SEQ * KSAVE) return;
    int j = i % KSAVE;
    int s = (i / KSAVE) % SEQ;
    int b = i / (KSAVE * SEQ);
    int c = g_topk[b * KSAVE + j];
    outp[i] = __half2float(g_x2h[(size_t)(b * SEQ + s) * ITR + c]);
}

// ---------------- launch ----------------
extern "C" void kernel_launch(void* const* d_in, const int* in_sizes, int n_in,
                              void* d_out, int out_size) {
    const float* x1      = (const float*)d_in[0];
    const float* w_up    = (const float*)d_in[1];
    const float* w_up_la = (const float*)d_in[2];
    const float* w_up_lb = (const float*)d_in[3];
    const float* w_down  = (const float*)d_in[4];
    const float* w_dn_la = (const float*)d_in[5];
    const float* w_dn_lb = (const float*)d_in[6];
    float* out = (float*)d_out;

    float *pup, *pdn, *wupT32;
    __half *x1h, *wupT, *x2h, *wdnT;
    cudaGetSymbolAddress((void**)&pup, g_pup);
    cudaGetSymbolAddress((void**)&pdn, g_pdn);
    cudaGetSymbolAddress((void**)&x1h, g_x1h);
    cudaGetSymbolAddress((void**)&wupT, g_wupT);
    cudaGetSymbolAddress((void**)&wupT32, g_wupT32);
    cudaGetSymbolAddress((void**)&x2h, g_x2h);
    cudaGetSymbolAddress((void**)&wdnT, g_wdnT);

    constexpr int DS1 = NSTAGE * (128 * BK * 2 + BN * BK * 2);   // 73728
    constexpr int DS2 = NSTAGE * (64 * BK * 2 + BN * BK * 2);    // 61440
    cudaFuncSetAttribute(gemm_f16<128, 0, 1>, cudaFuncAttributeMaxDynamicSharedMemorySize, DS1);
    cudaFuncSetAttribute(gemm_f16<64, 1, 0>, cudaFuncAttributeMaxDynamicSharedMemorySize, DS2);

    // launch order: gemm1 is the 4th launch => profiled by ncu (-s window)
    lora_proj_init<<<MTOK / 16, 256>>>(x1, w_up_la, pup, HID);                   // 1
    {
        size_t n4 = (size_t)MTOK * HID / 4;
        to_half<<<(unsigned)((n4 + 255) / 256), 256>>>(x1, x1h, n4);             // 2
    }
    split_T_dual<<<dim3(ITR / 32, HID / 32), dim3(32, 8)>>>(w_up, wupT, wupT32, HID, ITR);  // 3
    gemm_f16<128, 0, 1><<<dim3(MTOK / 128, ITR / BN), NT, DS1>>>(                // 4  <-- profiled
        x1h, wupT, pup, w_up_lb, w_dn_la, (float*)nullptr, x2h, MTOK, ITR, HID);

    split_T<<<dim3(HID / 32, ITR / 32), dim3(32, 8)>>>(w_down, wdnT, ITR, HID);  // 5
    fixup<<<512, 256>>>(x1, wupT32, w_up_lb);                                    // 6
    topk_kernel<<<NB, 256>>>();                                                  // 7
    gemm_f16<64, 1, 0><<<dim3(HID / BN, MTOK / 64), NT, DS2>>>(                  // 8
        x2h, wdnT, pdn, w_dn_lb, (float*)nullptr, out, (__half*)nullptr, MTOK, HID, ITR);

    int save_elems = NB * SEQ * KSAVE;
    gather_save<<<(save_elems + 255) / 256, 256>>>(out + (out_size - save_elems)); // 9
}